// round 2
// baseline (speedup 1.0000x reference)
#include <cuda_runtime.h>
#include <cstdint>

#define DINL __device__ __forceinline__
#define SCALE_F 0.022097086912079608f  // 1/sqrt(2048)

// ---------- scratch (__device__ globals; no allocation) ----------
__device__ float g_J[640 * 2048];            // joint [b*10+t][e]
__device__ float g_K[2 * 64 * 1024 * 12];    // keys, SCALE folded, padded to 12
__device__ float g_V[2 * 640 * 1024];        // values [r][b*10+t][d]
__device__ float g_O[2 * 640 * 2048];        // relu(tanh(weighted)) [r*640+row][e]
__device__ float g_F[1280 * 1024];           // fc_fusion out [r*640+row][d]

DINL float tanh_fast(float x) {
    float e = __expf(2.0f * x);              // inf/0 at extremes -> +/-1 exactly
    return 1.0f - __fdividef(2.0f, e + 1.0f);
}

DINL float* bufptr(int sel) {
    switch (sel) {
        case 0: return g_J;
        case 1: return g_V;
        case 2: return g_V + 640 * 1024;
        case 3: return g_O;
        default: return g_F;
    }
}

// ---------- tiny key linears: g_K[r][b][d][t] = SCALE*(sum_t' X[b][t'][d]*Wk[t'][t] + bk[t]) ----------
__global__ __launch_bounds__(256) void k_key(
    const float* __restrict__ audio, const float* __restrict__ video,
    const float* __restrict__ Wk1, const float* __restrict__ bk1,
    const float* __restrict__ Wk2, const float* __restrict__ bk2)
{
    int b = blockIdx.x, r = blockIdx.y;
    const float* X  = r ? video : audio;
    const float* Wk = r ? Wk2 : Wk1;
    const float* bk = r ? bk2 : bk1;
    __shared__ float sW[100], sb[10];
    if (threadIdx.x < 100) sW[threadIdx.x] = Wk[threadIdx.x];
    if (threadIdx.x < 10)  sb[threadIdx.x] = bk[threadIdx.x];
    __syncthreads();
    const float* xb = X + (size_t)b * 10240;
    float* kout = g_K + (size_t)(r * 64 + b) * 12288;
    for (int d = threadIdx.x; d < 1024; d += 256) {
        float a[10];
        #pragma unroll
        for (int t = 0; t < 10; ++t) a[t] = xb[t * 1024 + d];
        #pragma unroll
        for (int t = 0; t < 10; ++t) {
            float s = sb[t];
            #pragma unroll
            for (int tp = 0; tp < 10; ++tp) s += a[tp] * sW[tp * 10 + t];
            kout[d * 12 + t] = s * SCALE_F;
        }
        kout[d * 12 + 10] = 0.0f;
        kout[d * 12 + 11] = 0.0f;
    }
}

// ---------- generic fp32 GEMM: C[i][j] = sum_k A[i][k]*W[k][j] + bias[j] (opt relu) ----------
// A[i][k] = (k < Asplit) ? A0[i*lda + k] : A1[i*lda + k - Asplit]
// Tiles: 64x64, K-step 16, 256 threads, 4x4 per thread. M,N,K all multiples of tile dims.
__global__ __launch_bounds__(256) void k_gemm(
    const float* __restrict__ A0, const float* __restrict__ A1,
    int aSel, int Asplit, int lda,
    const float* __restrict__ W, const float* __restrict__ bias,
    int cSel, int M, int N, int K, int doRelu)
{
    __shared__ float As[16][64];
    __shared__ float Bs[16][64];
    const float* Ap0 = (aSel < 0) ? A0 : bufptr(aSel);
    const float* Ap1 = (aSel < 0) ? A1 : Ap0;
    float* C = bufptr(cSel);

    int tid = threadIdx.x;
    int tx = tid & 15, ty = tid >> 4;
    int row0 = blockIdx.y * 64, col0 = blockIdx.x * 64;
    float acc[4][4] = {};

    int lm  = tid >> 2;          // A load: row 0..63
    int lk4 = (tid & 3) * 4;     // A load: col group
    int bk  = tid >> 4;          // B load: row 0..15
    int bn4 = (tid & 15) * 4;    // B load: col group

    for (int kt = 0; kt < K; kt += 16) {
        int gk = kt + lk4;
        const float* ap = (gk < Asplit)
            ? (Ap0 + (size_t)(row0 + lm) * lda + gk)
            : (Ap1 + (size_t)(row0 + lm) * lda + (gk - Asplit));
        float4 av = *(const float4*)ap;
        As[lk4 + 0][lm] = av.x; As[lk4 + 1][lm] = av.y;
        As[lk4 + 2][lm] = av.z; As[lk4 + 3][lm] = av.w;
        float4 bv = *(const float4*)(W + (size_t)(kt + bk) * N + col0 + bn4);
        *(float4*)&Bs[bk][bn4] = bv;
        __syncthreads();
        #pragma unroll
        for (int kk = 0; kk < 16; ++kk) {
            float4 a = *(const float4*)&As[kk][ty * 4];
            float4 b = *(const float4*)&Bs[kk][tx * 4];
            float aa[4] = {a.x, a.y, a.z, a.w};
            float bb[4] = {b.x, b.y, b.z, b.w};
            #pragma unroll
            for (int i = 0; i < 4; ++i)
                #pragma unroll
                for (int j = 0; j < 4; ++j) acc[i][j] += aa[i] * bb[j];
        }
        __syncthreads();
    }
    #pragma unroll
    for (int i = 0; i < 4; ++i) {
        float4 o;
        float* op = &o.x;
        #pragma unroll
        for (int j = 0; j < 4; ++j) {
            float v = acc[i][j] + bias[col0 + tx * 4 + j];
            if (doRelu) v = fmaxf(v, 0.0f);
            op[j] = v;
        }
        *(float4*)(C + (size_t)(row0 + ty * 4 + i) * N + col0 + tx * 4) = o;
    }
}

// ---------- fused co-attention branch: per (eblk, b, r) ----------
// weighted[t,e] = tanh( sum_d V[t,d] * tanh( K[d,:].J[:,e] ) );  g_O = relu(weighted)
__global__ __launch_bounds__(256, 2) void k_branch()
{
    extern __shared__ float sm[];
    float* Ks = sm;              // [1024][12]
    float* Vs = sm + 12288;      // [1024][12] transposed V
    int eblk = blockIdx.x, b = blockIdx.y, r = blockIdx.z;

    const float* gk = g_K + (size_t)(r * 64 + b) * 12288;
    for (int i = threadIdx.x; i < 3072; i += 256)
        ((float4*)Ks)[i] = ((const float4*)gk)[i];
    const float* gv = g_V + (size_t)r * 640 * 1024 + (size_t)b * 10240;
    for (int t = 0; t < 10; ++t)
        for (int d = threadIdx.x; d < 1024; d += 256)
            Vs[d * 12 + t] = gv[t * 1024 + d];
    for (int d = threadIdx.x; d < 1024; d += 256) {
        Vs[d * 12 + 10] = 0.0f; Vs[d * 12 + 11] = 0.0f;
    }
    __syncthreads();

    int e0 = eblk * 1024 + threadIdx.x * 4;
    float J[10][4];
    const float* jb = g_J + (size_t)b * 20480 + e0;
    #pragma unroll
    for (int t = 0; t < 10; ++t) {
        float4 v = *(const float4*)(jb + (size_t)t * 2048);
        J[t][0] = v.x; J[t][1] = v.y; J[t][2] = v.z; J[t][3] = v.w;
    }
    float acc[10][4] = {};

    for (int d = 0; d < 1024; ++d) {
        const float4* kr = (const float4*)(Ks + d * 12);
        float4 k0 = kr[0], k1 = kr[1], k2 = kr[2];
        const float4* vr = (const float4*)(Vs + d * 12);
        float4 v0 = vr[0], v1 = vr[1], v2 = vr[2];
        float kk[10] = {k0.x, k0.y, k0.z, k0.w, k1.x, k1.y, k1.z, k1.w, k2.x, k2.y};
        float vv[10] = {v0.x, v0.y, v0.z, v0.w, v1.x, v1.y, v1.z, v1.w, v2.x, v2.y};
        #pragma unroll
        for (int j = 0; j < 4; ++j) {
            float s = kk[0] * J[0][j];
            #pragma unroll
            for (int t = 1; t < 10; ++t) s += kk[t] * J[t][j];
            s = tanh_fast(s);
            #pragma unroll
            for (int t = 0; t < 10; ++t) acc[t][j] += vv[t] * s;
        }
    }

    float* go = g_O + ((size_t)r * 640 + b * 10) * 2048 + e0;
    #pragma unroll
    for (int t = 0; t < 10; ++t) {
        float4 o;
        o.x = fmaxf(tanh_fast(acc[t][0]), 0.0f);
        o.y = fmaxf(tanh_fast(acc[t][1]), 0.0f);
        o.z = fmaxf(tanh_fast(acc[t][2]), 0.0f);
        o.w = fmaxf(tanh_fast(acc[t][3]), 0.0f);
        *(float4*)(go + (size_t)t * 2048) = o;
    }
}

// ---------- final: out = audio + video + fuse1 + fuse2 ----------
__global__ __launch_bounds__(256) void k_final(
    const float* __restrict__ audio, const float* __restrict__ video,
    float* __restrict__ out)
{
    int i = blockIdx.x * 256 + threadIdx.x;
    out[i] = audio[i] + video[i] + g_F[i] + g_F[640 * 1024 + i];
}

extern "C" void kernel_launch(void* const* d_in, const int* in_sizes, int n_in,
                              void* d_out, int out_size)
{
    const float* audio = (const float*)d_in[0];
    const float* video = (const float*)d_in[1];
    const float* Wq  = (const float*)d_in[2];
    const float* bq  = (const float*)d_in[3];
    const float* Wk1 = (const float*)d_in[4];
    const float* bk1 = (const float*)d_in[5];
    const float* Wk2 = (const float*)d_in[6];
    const float* bk2 = (const float*)d_in[7];
    const float* Wv1 = (const float*)d_in[8];
    const float* bv1 = (const float*)d_in[9];
    const float* Wv2 = (const float*)d_in[10];
    const float* bv2 = (const float*)d_in[11];
    const float* Wf  = (const float*)d_in[12];
    const float* bf  = (const float*)d_in[13];
    float* out = (float*)d_out;

    // keys (tiny)
    k_key<<<dim3(64, 2), 256>>>(audio, video, Wk1, bk1, Wk2, bk2);
    // joint = concat(audio,video) @ Wq + bq   [640 x 2048], K=2048
    k_gemm<<<dim3(32, 10), 256>>>(audio, video, -1, 1024, 1024, Wq, bq, 0, 640, 2048, 2048, 0);
    // val1 = audio @ Wv1 + bv1   [640 x 1024], K=1024
    k_gemm<<<dim3(16, 10), 256>>>(audio, audio, -1, 1024, 1024, Wv1, bv1, 1, 640, 1024, 1024, 0);
    // val2 = video @ Wv2 + bv2
    k_gemm<<<dim3(16, 10), 256>>>(video, video, -1, 1024, 1024, Wv2, bv2, 2, 640, 1024, 1024, 0);
    // fused attention branches
    cudaFuncSetAttribute(k_branch, cudaFuncAttributeMaxDynamicSharedMemorySize, 98304);
    k_branch<<<dim3(2, 64, 2), 256, 98304>>>();
    // fuse = relu(g_O @ Wf + bf)   [1280 x 1024], K=2048
    k_gemm<<<dim3(16, 20), 256>>>(nullptr, nullptr, 3, 2048, 2048, Wf, bf, 4, 1280, 1024, 2048, 1);
    // final add
    k_final<<<2560, 256>>>(audio, video, out);
}

// round 3
// speedup vs baseline: 1.5516x; 1.5516x over previous
#include <cuda_runtime.h>
#include <cstdint>

#define DINL __device__ __forceinline__
#define SCALE_F 0.022097086912079608f  // 1/sqrt(2048)

// ---------- scratch (__device__ globals; no allocation) ----------
__device__ float g_J[640 * 2048];            // joint [b*10+t][e]
__device__ float g_K[2 * 64 * 1024 * 16];    // keys, SCALE folded, [r][b][d][16] (t>=10 zero)
__device__ float g_V[2 * 640 * 1024];        // values [r][b*10+t][d]
__device__ float g_O[2 * 640 * 2048];        // relu(tanh(weighted)) [r*640+b*10+t][e]
__device__ float g_F[1280 * 1024];           // fc_fusion out

DINL float tanh_fast(float x) {
    float e = __expf(2.0f * x);              // exact +/-1 at extremes
    return 1.0f - __fdividef(2.0f, e + 1.0f);
}
DINL float f2tf(float x) {                   // round-to-nearest tf32 (kill truncation bias)
    uint32_t r; asm("cvt.rna.tf32.f32 %0, %1;" : "=r"(r) : "f"(x));
    return __uint_as_float(r);
}
DINL void mma8(float* c, float a0, float a1, float a2, float a3, float b0, float b1) {
    asm volatile(
        "mma.sync.aligned.m16n8k8.row.col.f32.tf32.tf32.f32 "
        "{%0,%1,%2,%3},{%4,%5,%6,%7},{%8,%9},{%0,%1,%2,%3};"
        : "+f"(c[0]), "+f"(c[1]), "+f"(c[2]), "+f"(c[3])
        : "r"(__float_as_uint(a0)), "r"(__float_as_uint(a1)),
          "r"(__float_as_uint(a2)), "r"(__float_as_uint(a3)),
          "r"(__float_as_uint(b0)), "r"(__float_as_uint(b1)));
}

DINL float* bufptr(int sel) {
    switch (sel) {
        case 0: return g_J;
        case 1: return g_V;
        case 2: return g_V + 640 * 1024;
        case 3: return g_O;
        default: return g_F;
    }
}

// ---------- tiny key linears: g_K[r][b][d][t] = SCALE*(sum_t' X[b][t'][d]*Wk[t'][t] + bk[t]) ----------
__global__ __launch_bounds__(256) void k_key(
    const float* __restrict__ audio, const float* __restrict__ video,
    const float* __restrict__ Wk1, const float* __restrict__ bk1,
    const float* __restrict__ Wk2, const float* __restrict__ bk2)
{
    int b = blockIdx.x, r = blockIdx.y;
    const float* X  = r ? video : audio;
    const float* Wk = r ? Wk2 : Wk1;
    const float* bk = r ? bk2 : bk1;
    __shared__ float sW[100], sb[10];
    if (threadIdx.x < 100) sW[threadIdx.x] = Wk[threadIdx.x];
    if (threadIdx.x < 10)  sb[threadIdx.x] = bk[threadIdx.x];
    __syncthreads();
    const float* xb = X + (size_t)b * 10240;
    float* kout = g_K + (size_t)(r * 64 + b) * 16384;
    for (int d = threadIdx.x; d < 1024; d += 256) {
        float a[10];
        #pragma unroll
        for (int t = 0; t < 10; ++t) a[t] = xb[t * 1024 + d];
        #pragma unroll
        for (int t = 0; t < 10; ++t) {
            float s = sb[t];
            #pragma unroll
            for (int tp = 0; tp < 10; ++tp) s += a[tp] * sW[tp * 10 + t];
            kout[d * 16 + t] = s * SCALE_F;
        }
        #pragma unroll
        for (int t = 10; t < 16; ++t) kout[d * 16 + t] = 0.0f;
    }
}

// ---------- tf32 tensor-core GEMM: C = A @ W + bias (opt relu) ----------
// BM=64, BN=128, BK=16. 256 threads = 8 warps (2m x 4n), warp tile 32x32.
// A[i][k] = (k < Asplit) ? A0[i*lda+k] : A1[i*lda+k-Asplit]
__global__ __launch_bounds__(256) void k_gemm_tc(
    const float* A0, const float* A1, int aSel, int Asplit, int lda,
    const float* __restrict__ W, const float* __restrict__ bias,
    int cSel, int M, int N, int K, int doRelu)
{
    __shared__ float As[64][20];    // [m][k], pad 4
    __shared__ float Bs[16][132];   // [k][n], pad 4
    const float* Ap0 = (aSel < 0) ? A0 : bufptr(aSel);
    const float* Ap1 = (aSel < 0) ? A1 : Ap0;
    float* C = bufptr(cSel);

    int tid = threadIdx.x, lane = tid & 31, warp = tid >> 5;
    int wm = (warp >> 2) * 32, wn = (warp & 3) * 32;
    int row0 = blockIdx.y * 64, col0 = blockIdx.x * 128;
    float acc[2][4][4] = {};

    int arow = tid >> 2, ak4 = (tid & 3) * 4;

    for (int kt = 0; kt < K; kt += 16) {
        int gk = kt + ak4;
        const float* ap = (gk < Asplit)
            ? (Ap0 + (size_t)(row0 + arow) * lda + gk)
            : (Ap1 + (size_t)(row0 + arow) * lda + (gk - Asplit));
        float4 av = *(const float4*)ap;
        As[arow][ak4 + 0] = f2tf(av.x); As[arow][ak4 + 1] = f2tf(av.y);
        As[arow][ak4 + 2] = f2tf(av.z); As[arow][ak4 + 3] = f2tf(av.w);
        #pragma unroll
        for (int i = 0; i < 2; ++i) {
            int idx = tid + i * 256;
            int bk = idx >> 5, bn4 = (idx & 31) * 4;
            float4 bv = *(const float4*)(W + (size_t)(kt + bk) * N + col0 + bn4);
            Bs[bk][bn4 + 0] = f2tf(bv.x); Bs[bk][bn4 + 1] = f2tf(bv.y);
            Bs[bk][bn4 + 2] = f2tf(bv.z); Bs[bk][bn4 + 3] = f2tf(bv.w);
        }
        __syncthreads();
        #pragma unroll
        for (int ks = 0; ks < 16; ks += 8) {
            float a[2][4];
            #pragma unroll
            for (int mi = 0; mi < 2; ++mi) {
                int rr = wm + mi * 16 + (lane >> 2), kk = ks + (lane & 3);
                a[mi][0] = As[rr][kk];     a[mi][1] = As[rr + 8][kk];
                a[mi][2] = As[rr][kk + 4]; a[mi][3] = As[rr + 8][kk + 4];
            }
            #pragma unroll
            for (int ni = 0; ni < 4; ++ni) {
                int nn = wn + ni * 8 + (lane >> 2), kk = ks + (lane & 3);
                float b0 = Bs[kk][nn], b1 = Bs[kk + 4][nn];
                mma8(acc[0][ni], a[0][0], a[0][1], a[0][2], a[0][3], b0, b1);
                mma8(acc[1][ni], a[1][0], a[1][1], a[1][2], a[1][3], b0, b1);
            }
        }
        __syncthreads();
    }
    #pragma unroll
    for (int mi = 0; mi < 2; ++mi)
        #pragma unroll
        for (int ni = 0; ni < 4; ++ni) {
            int rr = row0 + wm + mi * 16 + (lane >> 2);
            int cc = col0 + wn + ni * 8 + 2 * (lane & 3);
            float b0v = bias[cc], b1v = bias[cc + 1];
            float v0 = acc[mi][ni][0] + b0v, v1 = acc[mi][ni][1] + b1v;
            float v2 = acc[mi][ni][2] + b0v, v3 = acc[mi][ni][3] + b1v;
            if (doRelu) {
                v0 = fmaxf(v0, 0.f); v1 = fmaxf(v1, 0.f);
                v2 = fmaxf(v2, 0.f); v3 = fmaxf(v3, 0.f);
            }
            *(float2*)(C + (size_t)rr * N + cc) = make_float2(v0, v1);
            *(float2*)(C + (size_t)(rr + 8) * N + cc) = make_float2(v2, v3);
        }
}

// ---------- fused co-attention branch, tensor cores ----------
// Per CTA (eblk of 128, b, r):  S^T[e,d] = tanh(sum_t J[t,e]*K[d,t]);
// W^T[e,t] = sum_d S^T[e,d]*V[t,d];  g_O[t][e] = relu(tanh(W^T)).
// 8 warps, each owns 16 e-rows. d processed in 16 chunks of 64.
#define SJ_OFF 0                       // [128][20]  J^T rounded, [e][t]
#define SK_OFF (128 * 20)              // [64][20]   K chunk, [d][t]
#define SV_OFF (SK_OFF + 64 * 20)      // [16][66]   V chunk, [t][d]
#define SS_OFF (SV_OFF + 16 * 66)      // [128][68]  S^T tile (per-warp private rows)
#define SM_FLOATS (SS_OFF + 128 * 68)  // 13600 floats = 54400 B

__global__ __launch_bounds__(256) void k_branch_tc()
{
    extern __shared__ float sm[];
    float* sJ = sm + SJ_OFF;
    float* sK = sm + SK_OFF;
    float* sV = sm + SV_OFF;
    float* sS = sm + SS_OFF;
    int eblk = blockIdx.x, b = blockIdx.y, r = blockIdx.z;
    int tid = threadIdx.x, lane = tid & 31, warp = tid >> 5;
    int ew = warp * 16;

    // stage J^T for this e-block: sJ[e][t], t>=10 zero
    for (int i = tid; i < 2048; i += 256) {
        int e = i & 127, t = i >> 7;
        float v = (t < 10) ? g_J[(size_t)(b * 10 + t) * 2048 + eblk * 128 + e] : 0.0f;
        sJ[e * 20 + t] = f2tf(v);
    }

    const float* gk  = g_K + (size_t)(r * 64 + b) * 16384;
    const float* gvb = g_V + (size_t)r * 655360 + (size_t)b * 10240;

    float accW[2][4] = {};

    for (int ch = 0; ch < 16; ++ch) {
        __syncthreads();
        {   // stage K chunk [64][16] -> sK[d][t]
            int d = tid >> 2, k4 = (tid & 3) * 4;
            float4 v = *(const float4*)(gk + (size_t)(ch * 64 + d) * 16 + k4);
            sK[d * 20 + k4 + 0] = f2tf(v.x); sK[d * 20 + k4 + 1] = f2tf(v.y);
            sK[d * 20 + k4 + 2] = f2tf(v.z); sK[d * 20 + k4 + 3] = f2tf(v.w);
        }
        {   // stage V chunk [16][64] -> sV[t][d], t>=10 zero
            int t = tid >> 4, d4 = (tid & 15) * 4;
            float4 v = (t < 10) ? *(const float4*)(gvb + (size_t)t * 1024 + ch * 64 + d4)
                                : make_float4(0.f, 0.f, 0.f, 0.f);
            sV[t * 66 + d4 + 0] = f2tf(v.x); sV[t * 66 + d4 + 1] = f2tf(v.y);
            sV[t * 66 + d4 + 2] = f2tf(v.z); sV[t * 66 + d4 + 3] = f2tf(v.w);
        }
        __syncthreads();

        // GEMM1: accS[e 16][d 64] per warp, k = t (16 padded)
        float accS[8][4] = {};
        #pragma unroll
        for (int ks = 0; ks < 16; ks += 8) {
            int rr = ew + (lane >> 2), kk = ks + (lane & 3);
            float a0 = sJ[rr * 20 + kk],       a1 = sJ[(rr + 8) * 20 + kk];
            float a2 = sJ[rr * 20 + kk + 4],   a3 = sJ[(rr + 8) * 20 + kk + 4];
            #pragma unroll
            for (int ni = 0; ni < 8; ++ni) {
                int dd = ni * 8 + (lane >> 2);
                float b0 = sK[dd * 20 + kk], b1 = sK[dd * 20 + kk + 4];
                mma8(accS[ni], a0, a1, a2, a3, b0, b1);
            }
        }
        // tanh + round -> sS (warp-private rows, no CTA barrier needed)
        {
            int e0 = ew + (lane >> 2), d0 = 2 * (lane & 3);
            #pragma unroll
            for (int ni = 0; ni < 8; ++ni) {
                int dd = ni * 8 + d0;
                sS[e0 * 68 + dd]           = f2tf(tanh_fast(accS[ni][0]));
                sS[e0 * 68 + dd + 1]       = f2tf(tanh_fast(accS[ni][1]));
                sS[(e0 + 8) * 68 + dd]     = f2tf(tanh_fast(accS[ni][2]));
                sS[(e0 + 8) * 68 + dd + 1] = f2tf(tanh_fast(accS[ni][3]));
            }
        }
        __syncwarp();

        // GEMM2: accW[e 16][t 16] += S^T chunk @ V^T, k = d (64)
        #pragma unroll
        for (int ks = 0; ks < 64; ks += 8) {
            int rr = ew + (lane >> 2), kk = ks + (lane & 3);
            float a0 = sS[rr * 68 + kk],     a1 = sS[(rr + 8) * 68 + kk];
            float a2 = sS[rr * 68 + kk + 4], a3 = sS[(rr + 8) * 68 + kk + 4];
            #pragma unroll
            for (int nt = 0; nt < 2; ++nt) {
                int tt = nt * 8 + (lane >> 2);
                float b0 = sV[tt * 66 + kk], b1 = sV[tt * 66 + kk + 4];
                mma8(accW[nt], a0, a1, a2, a3, b0, b1);
            }
        }
        __syncwarp();   // protect sS before next chunk's overwrite (same warp)
    }

    // epilogue: g_O[r*640 + b*10 + t][e] = relu(tanh(accW))
    int e = eblk * 128 + ew + (lane >> 2);
    #pragma unroll
    for (int nt = 0; nt < 2; ++nt) {
        int t0 = nt * 8 + 2 * (lane & 3);
        #pragma unroll
        for (int j = 0; j < 2; ++j) {
            int t = t0 + j;
            if (t < 10) {
                size_t rowoff = ((size_t)r * 640 + b * 10 + t) * 2048;
                g_O[rowoff + e]     = fmaxf(tanh_fast(accW[nt][j]), 0.0f);
                g_O[rowoff + e + 8] = fmaxf(tanh_fast(accW[nt][2 + j]), 0.0f);
            }
        }
    }
}

// ---------- final: out = audio + video + fuse1 + fuse2 ----------
__global__ __launch_bounds__(256) void k_final(
    const float* __restrict__ audio, const float* __restrict__ video,
    float* __restrict__ out)
{
    int i = blockIdx.x * 256 + threadIdx.x;
    out[i] = audio[i] + video[i] + g_F[i] + g_F[640 * 1024 + i];
}

extern "C" void kernel_launch(void* const* d_in, const int* in_sizes, int n_in,
                              void* d_out, int out_size)
{
    const float* audio = (const float*)d_in[0];
    const float* video = (const float*)d_in[1];
    const float* Wq  = (const float*)d_in[2];
    const float* bq  = (const float*)d_in[3];
    const float* Wk1 = (const float*)d_in[4];
    const float* bk1 = (const float*)d_in[5];
    const float* Wk2 = (const float*)d_in[6];
    const float* bk2 = (const float*)d_in[7];
    const float* Wv1 = (const float*)d_in[8];
    const float* bv1 = (const float*)d_in[9];
    const float* Wv2 = (const float*)d_in[10];
    const float* bv2 = (const float*)d_in[11];
    const float* Wf  = (const float*)d_in[12];
    const float* bf  = (const float*)d_in[13];
    float* out = (float*)d_out;

    k_key<<<dim3(64, 2), 256>>>(audio, video, Wk1, bk1, Wk2, bk2);
    // joint = concat(audio,video) @ Wq + bq   [640 x 2048], K=2048
    k_gemm_tc<<<dim3(16, 10), 256>>>(audio, video, -1, 1024, 1024, Wq, bq, 0, 640, 2048, 2048, 0);
    // val1 = audio @ Wv1 + bv1   [640 x 1024]
    k_gemm_tc<<<dim3(8, 10), 256>>>(audio, audio, -1, 1024, 1024, Wv1, bv1, 1, 640, 1024, 1024, 0);
    // val2 = video @ Wv2 + bv2
    k_gemm_tc<<<dim3(8, 10), 256>>>(video, video, -1, 1024, 1024, Wv2, bv2, 2, 640, 1024, 1024, 0);
    // fused co-attention branches
    cudaFuncSetAttribute(k_branch_tc, cudaFuncAttributeMaxDynamicSharedMemorySize,
                         SM_FLOATS * sizeof(float));
    k_branch_tc<<<dim3(16, 64, 2), 256, SM_FLOATS * sizeof(float)>>>();
    // fuse = relu(g_O @ Wf + bf)  [1280 x 1024], K=2048
    k_gemm_tc<<<dim3(8, 20), 256>>>(nullptr, nullptr, 3, 2048, 2048, Wf, bf, 4, 1280, 1024, 2048, 1);
    k_final<<<2560, 256>>>(audio, video, out);
}

// round 4
// speedup vs baseline: 2.0973x; 1.3517x over previous
#include <cuda_runtime.h>
#include <cstdint>

#define DINL __device__ __forceinline__
#define SCALE_F 0.022097086912079608f  // 1/sqrt(2048)

// ---------- scratch ----------
__device__ float g_J[640 * 2048];            // joint, tf32-rounded
__device__ float g_K[2 * 64 * 1024 * 16];    // keys, SCALE folded, tf32-rounded, [r][b][d][16]
__device__ float g_V[2 * 640 * 1024];        // values, tf32-rounded
__device__ float g_O[2 * 640 * 2048];        // relu(tanh(weighted))
__device__ float g_F[1280 * 1024];           // fc_fusion out

DINL float tanhx(float x) {
    float y; asm("tanh.approx.f32 %0, %1;" : "=f"(y) : "f"(x)); return y;
}
DINL float f2tf(float x) {
    uint32_t r; asm("cvt.rna.tf32.f32 %0, %1;" : "=r"(r) : "f"(x));
    return __uint_as_float(r);
}
DINL void mma8(float* c, float a0, float a1, float a2, float a3, float b0, float b1) {
    asm volatile(
        "mma.sync.aligned.m16n8k8.row.col.f32.tf32.tf32.f32 "
        "{%0,%1,%2,%3},{%4,%5,%6,%7},{%8,%9},{%0,%1,%2,%3};"
        : "+f"(c[0]), "+f"(c[1]), "+f"(c[2]), "+f"(c[3])
        : "r"(__float_as_uint(a0)), "r"(__float_as_uint(a1)),
          "r"(__float_as_uint(a2)), "r"(__float_as_uint(a3)),
          "r"(__float_as_uint(b0)), "r"(__float_as_uint(b1)));
}
DINL float* bufptr(int sel) {
    switch (sel) {
        case 0: return g_J;
        case 1: return g_V;
        case 3: return g_O;
        default: return g_F;
    }
}

// ---------- key linears: g_K[r][b][d][t] = tf32(SCALE*(X^T Wk + bk)) ----------
__global__ __launch_bounds__(256) void k_key(
    const float* __restrict__ audio, const float* __restrict__ video,
    const float* __restrict__ Wk1, const float* __restrict__ bk1,
    const float* __restrict__ Wk2, const float* __restrict__ bk2)
{
    int b = blockIdx.x, r = blockIdx.y;
    const float* X  = r ? video : audio;
    const float* Wk = r ? Wk2 : Wk1;
    const float* bk = r ? bk2 : bk1;
    __shared__ float sW[100], sb[10];
    if (threadIdx.x < 100) sW[threadIdx.x] = Wk[threadIdx.x];
    if (threadIdx.x < 10)  sb[threadIdx.x] = bk[threadIdx.x];
    __syncthreads();
    const float* xb = X + (size_t)b * 10240;
    float* kout = g_K + (size_t)(r * 64 + b) * 16384;
    for (int d = threadIdx.x; d < 1024; d += 256) {
        float a[10];
        #pragma unroll
        for (int t = 0; t < 10; ++t) a[t] = xb[t * 1024 + d];
        #pragma unroll
        for (int t = 0; t < 10; ++t) {
            float s = sb[t];
            #pragma unroll
            for (int tp = 0; tp < 10; ++tp) s += a[tp] * sW[tp * 10 + t];
            kout[d * 16 + t] = f2tf(s * SCALE_F);
        }
        #pragma unroll
        for (int t = 10; t < 16; ++t) kout[d * 16 + t] = 0.0f;
    }
}

// ---------- tf32 GEMM, double-buffered, 1 barrier/tile ----------
// BM=64, BN=128, BK=16; 8 warps (2m x 4n), warp tile 32x32.
// z = blockIdx.z selects operand set (for batching val1/val2).
__global__ __launch_bounds__(256) void k_gemm_tc(
    const float* A0, const float* A1, const float* A0z, const float* A1z,
    int aSel, int Asplit, int lda,
    const float* W0, const float* W1, const float* bias0, const float* bias1,
    int cSel, size_t cStride, int M, int N, int K, int doRelu, int doRound)
{
    __shared__ float As[2][64 * 20];
    __shared__ float Bs[2][16 * 132];
    int z = blockIdx.z;
    const float* Ap0, *Ap1;
    if (aSel < 0) { Ap0 = z ? A0z : A0; Ap1 = z ? A1z : A1; }
    else          { Ap0 = Ap1 = bufptr(aSel); }
    const float* W    = z ? W1 : W0;
    const float* bias = z ? bias1 : bias0;
    float* C = bufptr(cSel) + (size_t)z * cStride;

    int tid = threadIdx.x, lane = tid & 31, warp = tid >> 5;
    int g = lane >> 2, j = lane & 3;
    int wm = (warp >> 2) * 32, wn = (warp & 3) * 32;
    int row0 = blockIdx.y * 64, col0 = blockIdx.x * 128;
    float acc[2][4][4] = {};

    int arow = tid >> 2, ak4 = (tid & 3) * 4;
    int brow0 = tid >> 5, bn4 = (tid & 31) * 4;

    // prologue: tile 0
    {
        const float* ap = (ak4 < Asplit)
            ? (Ap0 + (size_t)(row0 + arow) * lda + ak4)
            : (Ap1 + (size_t)(row0 + arow) * lda + (ak4 - Asplit));
        float4 av = *(const float4*)ap;
        As[0][arow * 20 + ak4 + 0] = f2tf(av.x); As[0][arow * 20 + ak4 + 1] = f2tf(av.y);
        As[0][arow * 20 + ak4 + 2] = f2tf(av.z); As[0][arow * 20 + ak4 + 3] = f2tf(av.w);
        #pragma unroll
        for (int i = 0; i < 2; ++i) {
            int bk = brow0 + i * 8;
            float4 bv = *(const float4*)(W + (size_t)bk * N + col0 + bn4);
            Bs[0][bk * 132 + bn4 + 0] = f2tf(bv.x); Bs[0][bk * 132 + bn4 + 1] = f2tf(bv.y);
            Bs[0][bk * 132 + bn4 + 2] = f2tf(bv.z); Bs[0][bk * 132 + bn4 + 3] = f2tf(bv.w);
        }
    }
    __syncthreads();

    int buf = 0;
    for (int kt = 0; ; ) {
        int ktn = kt + 16;
        bool more = ktn < K;
        float4 aN, bN0, bN1;
        if (more) {
            int gk = ktn + ak4;
            const float* ap = (gk < Asplit)
                ? (Ap0 + (size_t)(row0 + arow) * lda + gk)
                : (Ap1 + (size_t)(row0 + arow) * lda + (gk - Asplit));
            aN  = *(const float4*)ap;
            bN0 = *(const float4*)(W + (size_t)(ktn + brow0) * N + col0 + bn4);
            bN1 = *(const float4*)(W + (size_t)(ktn + brow0 + 8) * N + col0 + bn4);
        }
        const float* Ab = As[buf];
        const float* Bb = Bs[buf];
        #pragma unroll
        for (int ks = 0; ks < 16; ks += 8) {
            float a[2][4];
            #pragma unroll
            for (int mi = 0; mi < 2; ++mi) {
                int rr = wm + mi * 16 + g, kk = ks + j;
                a[mi][0] = Ab[rr * 20 + kk];       a[mi][1] = Ab[(rr + 8) * 20 + kk];
                a[mi][2] = Ab[rr * 20 + kk + 4];   a[mi][3] = Ab[(rr + 8) * 20 + kk + 4];
            }
            #pragma unroll
            for (int ni = 0; ni < 4; ++ni) {
                int nn = wn + ni * 8 + g, kk = ks + j;
                float b0 = Bb[kk * 132 + nn], b1 = Bb[(kk + 4) * 132 + nn];
                mma8(acc[0][ni], a[0][0], a[0][1], a[0][2], a[0][3], b0, b1);
                mma8(acc[1][ni], a[1][0], a[1][1], a[1][2], a[1][3], b0, b1);
            }
        }
        if (!more) break;
        float* An = As[buf ^ 1];
        float* Bn = Bs[buf ^ 1];
        An[arow * 20 + ak4 + 0] = f2tf(aN.x); An[arow * 20 + ak4 + 1] = f2tf(aN.y);
        An[arow * 20 + ak4 + 2] = f2tf(aN.z); An[arow * 20 + ak4 + 3] = f2tf(aN.w);
        Bn[brow0 * 132 + bn4 + 0] = f2tf(bN0.x); Bn[brow0 * 132 + bn4 + 1] = f2tf(bN0.y);
        Bn[brow0 * 132 + bn4 + 2] = f2tf(bN0.z); Bn[brow0 * 132 + bn4 + 3] = f2tf(bN0.w);
        Bn[(brow0 + 8) * 132 + bn4 + 0] = f2tf(bN1.x); Bn[(brow0 + 8) * 132 + bn4 + 1] = f2tf(bN1.y);
        Bn[(brow0 + 8) * 132 + bn4 + 2] = f2tf(bN1.z); Bn[(brow0 + 8) * 132 + bn4 + 3] = f2tf(bN1.w);
        __syncthreads();
        buf ^= 1; kt = ktn;
    }

    #pragma unroll
    for (int mi = 0; mi < 2; ++mi)
        #pragma unroll
        for (int ni = 0; ni < 4; ++ni) {
            int rr = row0 + wm + mi * 16 + g;
            int cc = col0 + wn + ni * 8 + 2 * j;
            float b0v = bias[cc], b1v = bias[cc + 1];
            float v0 = acc[mi][ni][0] + b0v, v1 = acc[mi][ni][1] + b1v;
            float v2 = acc[mi][ni][2] + b0v, v3 = acc[mi][ni][3] + b1v;
            if (doRelu) {
                v0 = fmaxf(v0, 0.f); v1 = fmaxf(v1, 0.f);
                v2 = fmaxf(v2, 0.f); v3 = fmaxf(v3, 0.f);
            }
            if (doRound) { v0 = f2tf(v0); v1 = f2tf(v1); v2 = f2tf(v2); v3 = f2tf(v3); }
            *(float2*)(C + (size_t)rr * N + cc) = make_float2(v0, v1);
            *(float2*)(C + (size_t)(rr + 8) * N + cc) = make_float2(v2, v3);
        }
}

// ---------- fused co-attention branch: shfl relayout, no S smem ----------
// Per CTA (eblk 128, b, r): S^T[e,d]=tanh(J^T K^T); W^T[e,t]=S^T V^T; out relu(tanh).
__global__ __launch_bounds__(256) void k_branch_tc()
{
    __shared__ float sJ[128 * 20];
    __shared__ float sK[2][64 * 20];
    __shared__ float sV[2][16 * 68];

    int eblk = blockIdx.x, b = blockIdx.y, r = blockIdx.z;
    int tid = threadIdx.x, lane = tid & 31, warp = tid >> 5;
    int g = lane >> 2, j = lane & 3;
    int ew = warp * 16;
    int lo = (lane & ~3) | (j >> 1), hi = lo + 2;
    bool odd = j & 1;

    const float* gk  = g_K + (size_t)(r * 64 + b) * 16384;
    const float* gvb = g_V + (size_t)r * 655360 + (size_t)b * 10240;

    // stage J^T: sJ[e][t], zeros for t>=10  (g_J pre-rounded)
    #pragma unroll
    for (int i = tid; i < 2048; i += 256) {
        int e = i & 127, t = i >> 7;
        sJ[e * 20 + t] = (t < 10)
            ? g_J[(size_t)(b * 10 + t) * 2048 + eblk * 128 + e] : 0.0f;
    }
    // zero V pad rows (t=10..15) in both buffers
    for (int i = tid; i < 2 * 6 * 68; i += 256) {
        int bb = i / (6 * 68), rem = i - bb * 6 * 68;
        sV[bb][(10 + rem / 68) * 68 + (rem % 68)] = 0.0f;
    }
    // stage chunk 0
    {
        int d = tid >> 2, k4 = (tid & 3) * 4;
        float4 kv = *(const float4*)(gk + (size_t)d * 16 + k4);
        sK[0][d * 20 + k4 + 0] = kv.x; sK[0][d * 20 + k4 + 1] = kv.y;
        sK[0][d * 20 + k4 + 2] = kv.z; sK[0][d * 20 + k4 + 3] = kv.w;
        if (tid < 160) {
            int t = tid >> 4, d4 = (tid & 15) * 4;
            float4 vv = *(const float4*)(gvb + (size_t)t * 1024 + d4);
            sV[0][t * 68 + d4 + 0] = vv.x; sV[0][t * 68 + d4 + 1] = vv.y;
            sV[0][t * 68 + d4 + 2] = vv.z; sV[0][t * 68 + d4 + 3] = vv.w;
        }
    }
    __syncthreads();

    float accW[2][4] = {};

    for (int ch = 0; ch < 16; ++ch) {
        // prefetch next chunk into regs
        float4 kreg, vreg;
        bool more = (ch + 1) < 16;
        if (more) {
            int d = tid >> 2, k4 = (tid & 3) * 4;
            kreg = *(const float4*)(gk + (size_t)((ch + 1) * 64 + d) * 16 + k4);
            if (tid < 160) {
                int t = tid >> 4, d4 = (tid & 15) * 4;
                vreg = *(const float4*)(gvb + (size_t)t * 1024 + (ch + 1) * 64 + d4);
            }
        }
        const float* Kb = sK[ch & 1];
        const float* Vb = sV[ch & 1];

        // GEMM1: accS[e16][d64], k = t(16)
        float accS[8][4] = {};
        #pragma unroll
        for (int ks = 0; ks < 16; ks += 8) {
            int rr = ew + g, kk = ks + j;
            float a0 = sJ[rr * 20 + kk],     a1 = sJ[(rr + 8) * 20 + kk];
            float a2 = sJ[rr * 20 + kk + 4], a3 = sJ[(rr + 8) * 20 + kk + 4];
            #pragma unroll
            for (int ni = 0; ni < 8; ++ni) {
                int dd = ni * 8 + g;
                mma8(accS[ni], a0, a1, a2, a3, Kb[dd * 20 + kk], Kb[dd * 20 + kk + 4]);
            }
        }
        // tanh + shfl relayout + GEMM2 (k-step = ni tile)
        #pragma unroll
        for (int ni = 0; ni < 8; ++ni) {
            float c0 = f2tf(tanhx(accS[ni][0]));
            float c1 = f2tf(tanhx(accS[ni][1]));
            float c2 = f2tf(tanhx(accS[ni][2]));
            float c3 = f2tf(tanhx(accS[ni][3]));
            float v0 = __shfl_sync(0xffffffffu, c0, lo);
            float v1 = __shfl_sync(0xffffffffu, c1, lo);
            float a0 = odd ? v1 : v0;
            float u0 = __shfl_sync(0xffffffffu, c0, hi);
            float u1 = __shfl_sync(0xffffffffu, c1, hi);
            float a2 = odd ? u1 : u0;
            float w0 = __shfl_sync(0xffffffffu, c2, lo);
            float w1 = __shfl_sync(0xffffffffu, c3, lo);
            float a1 = odd ? w1 : w0;
            float w2 = __shfl_sync(0xffffffffu, c2, hi);
            float w3 = __shfl_sync(0xffffffffu, c3, hi);
            float a3 = odd ? w3 : w2;
            #pragma unroll
            for (int nt = 0; nt < 2; ++nt) {
                const float* Vrow = Vb + (nt * 8 + g) * 68 + ni * 8;
                mma8(accW[nt], a0, a1, a2, a3, Vrow[j], Vrow[j + 4]);
            }
        }
        if (more) {
            float* Kn = sK[(ch + 1) & 1];
            int d = tid >> 2, k4 = (tid & 3) * 4;
            Kn[d * 20 + k4 + 0] = kreg.x; Kn[d * 20 + k4 + 1] = kreg.y;
            Kn[d * 20 + k4 + 2] = kreg.z; Kn[d * 20 + k4 + 3] = kreg.w;
            if (tid < 160) {
                float* Vn = sV[(ch + 1) & 1];
                int t = tid >> 4, d4 = (tid & 15) * 4;
                Vn[t * 68 + d4 + 0] = vreg.x; Vn[t * 68 + d4 + 1] = vreg.y;
                Vn[t * 68 + d4 + 2] = vreg.z; Vn[t * 68 + d4 + 3] = vreg.w;
            }
            __syncthreads();
        }
    }

    // epilogue: g_O[(r*640+b*10+t)][e] = relu(tanh(accW))
    int e = eblk * 128 + ew + g;
    #pragma unroll
    for (int nt = 0; nt < 2; ++nt) {
        #pragma unroll
        for (int jj = 0; jj < 2; ++jj) {
            int t = nt * 8 + 2 * j + jj;
            if (t < 10) {
                size_t rowoff = ((size_t)r * 640 + b * 10 + t) * 2048;
                g_O[rowoff + e]     = fmaxf(tanhx(accW[nt][jj]), 0.0f);
                g_O[rowoff + e + 8] = fmaxf(tanhx(accW[nt][2 + jj]), 0.0f);
            }
        }
    }
}

// ---------- final: out = audio + video + fuse1 + fuse2 ----------
__global__ __launch_bounds__(256) void k_final(
    const float* __restrict__ audio, const float* __restrict__ video,
    float* __restrict__ out)
{
    int i = blockIdx.x * 256 + threadIdx.x;
    out[i] = audio[i] + video[i] + g_F[i] + g_F[640 * 1024 + i];
}

extern "C" void kernel_launch(void* const* d_in, const int* in_sizes, int n_in,
                              void* d_out, int out_size)
{
    const float* audio = (const float*)d_in[0];
    const float* video = (const float*)d_in[1];
    const float* Wq  = (const float*)d_in[2];
    const float* bq  = (const float*)d_in[3];
    const float* Wk1 = (const float*)d_in[4];
    const float* bk1 = (const float*)d_in[5];
    const float* Wk2 = (const float*)d_in[6];
    const float* bk2 = (const float*)d_in[7];
    const float* Wv1 = (const float*)d_in[8];
    const float* bv1 = (const float*)d_in[9];
    const float* Wv2 = (const float*)d_in[10];
    const float* bv2 = (const float*)d_in[11];
    const float* Wf  = (const float*)d_in[12];
    const float* bf  = (const float*)d_in[13];
    float* out = (float*)d_out;

    k_key<<<dim3(64, 2), 256>>>(audio, video, Wk1, bk1, Wk2, bk2);
    // joint = concat(audio,video) @ Wq + bq  [640x2048] K=2048, rounded
    k_gemm_tc<<<dim3(16, 10), 256>>>(audio, video, audio, video, -1, 1024, 1024,
                                     Wq, Wq, bq, bq, 0, 0, 640, 2048, 2048, 0, 1);
    // val1/val2 batched over z  [640x1024] K=1024, rounded
    k_gemm_tc<<<dim3(8, 10, 2), 256>>>(audio, audio, video, video, -1, 1024, 1024,
                                       Wv1, Wv2, bv1, bv2, 1, (size_t)640 * 1024,
                                       640, 1024, 1024, 0, 1);
    // fused co-attention branches
    k_branch_tc<<<dim3(16, 64, 2), 256>>>();
    // fuse = relu(g_O @ Wf + bf)  [1280x1024] K=2048
    k_gemm_tc<<<dim3(8, 20), 256>>>(nullptr, nullptr, nullptr, nullptr, 3, 2048, 2048,
                                    Wf, Wf, bf, bf, 4, 0, 1280, 1024, 2048, 1, 0);
    k_final<<<2560, 256>>>(audio, video, out);
}

// round 5
// speedup vs baseline: 2.3950x; 1.1419x over previous
#include <cuda_runtime.h>
#include <cstdint>

#define DINL __device__ __forceinline__
#define SCALE_F 0.022097086912079608f  // 1/sqrt(2048)

// ---------- scratch ----------
__device__ float g_J[640 * 2048];            // joint, tf32-rounded, natural layout
__device__ float g_K[2 * 64 * 1024 * 16];    // keys, SCALE folded, tf32, d-rows PERMUTED
__device__ float g_V[2 * 640 * 1024];        // values, tf32, d-cols PERMUTED
__device__ float g_O[2 * 640 * 2048];        // relu(tanh(weighted)), natural
__device__ float g_F[1280 * 1024];           // fc_fusion out

DINL float tanhx(float x) {
    float y; asm("tanh.approx.f32 %0, %1;" : "=f"(y) : "f"(x)); return y;
}
DINL float f2tf(float x) {
    uint32_t r; asm("cvt.rna.tf32.f32 %0, %1;" : "=r"(r) : "f"(x));
    return __uint_as_float(r);
}
DINL void mma8(float* c, float a0, float a1, float a2, float a3, float b0, float b1) {
    asm volatile(
        "mma.sync.aligned.m16n8k8.row.col.f32.tf32.tf32.f32 "
        "{%0,%1,%2,%3},{%4,%5,%6,%7},{%8,%9},{%0,%1,%2,%3};"
        : "+f"(c[0]), "+f"(c[1]), "+f"(c[2]), "+f"(c[3])
        : "r"(__float_as_uint(a0)), "r"(__float_as_uint(a1)),
          "r"(__float_as_uint(a2)), "r"(__float_as_uint(a3)),
          "r"(__float_as_uint(b0)), "r"(__float_as_uint(b1)));
}
DINL int dperm(int c) {  // storage position of physical in-group index
    return (c & ~7) + 2 * (c & 3) + ((c & 7) >> 2);
}
DINL float* bufptr(int sel) {
    switch (sel) {
        case 0: return g_J;
        case 1: return g_V;
        case 3: return g_O;
        default: return g_F;
    }
}

// ---------- key linears: permuted rows ----------
__global__ __launch_bounds__(256) void k_key(
    const float* __restrict__ audio, const float* __restrict__ video,
    const float* __restrict__ Wk1, const float* __restrict__ bk1,
    const float* __restrict__ Wk2, const float* __restrict__ bk2)
{
    int b = blockIdx.x, r = blockIdx.y;
    const float* X  = r ? video : audio;
    const float* Wk = r ? Wk2 : Wk1;
    const float* bk = r ? bk2 : bk1;
    __shared__ float sW[100], sb[10];
    if (threadIdx.x < 100) sW[threadIdx.x] = Wk[threadIdx.x];
    if (threadIdx.x < 10)  sb[threadIdx.x] = bk[threadIdx.x];
    __syncthreads();
    const float* xb = X + (size_t)b * 10240;
    float* kout = g_K + (size_t)(r * 64 + b) * 16384;
    for (int d = threadIdx.x; d < 1024; d += 256) {
        float a[10];
        #pragma unroll
        for (int t = 0; t < 10; ++t) a[t] = xb[t * 1024 + d];
        float* krow = kout + (size_t)dperm(d) * 16;
        #pragma unroll
        for (int t = 0; t < 10; ++t) {
            float s = sb[t];
            #pragma unroll
            for (int tp = 0; tp < 10; ++tp) s += a[tp] * sW[tp * 10 + t];
            krow[t] = f2tf(s * SCALE_F);
        }
        #pragma unroll
        for (int t = 10; t < 16; ++t) krow[t] = 0.0f;
    }
}

// ---------- tf32 GEMM: BM=64 BN=128 BK=32, double-buffered ----------
__global__ __launch_bounds__(256) void k_gemm_tc(
    const float* A0, const float* A1, const float* A0z, const float* A1z,
    int aSel, int Asplit, int lda,
    const float* W0, const float* W1, const float* bias0, const float* bias1,
    int cSel, size_t cStride, int M, int N, int K,
    int doRelu, int doRound, int doPerm)
{
    extern __shared__ float smg[];
    float* As = smg;                  // [2][64*36]
    float* Bs = smg + 2 * 2304;       // [2][32*132]
    int z = blockIdx.z;
    const float* Ap0, *Ap1;
    if (aSel < 0) { Ap0 = z ? A0z : A0; Ap1 = z ? A1z : A1; }
    else          { Ap0 = Ap1 = bufptr(aSel); }
    const float* W    = z ? W1 : W0;
    const float* bias = z ? bias1 : bias0;
    float* C = bufptr(cSel) + (size_t)z * cStride;

    int tid = threadIdx.x, lane = tid & 31, warp = tid >> 5;
    int g = lane >> 2, j = lane & 3;
    int wm = (warp >> 2) * 32, wn = (warp & 3) * 32;
    int row0 = blockIdx.y * 64, col0 = blockIdx.x * 128;
    float acc[2][4][4] = {};

    int arow = tid >> 2, acol = (tid & 3) * 8;
    int brow = tid >> 5, bn4 = (tid & 31) * 4;

    // prologue: stage 0
    #pragma unroll
    for (int h = 0; h < 2; ++h) {
        int gk = acol + h * 4;
        const float* ap = (gk < Asplit)
            ? (Ap0 + (size_t)(row0 + arow) * lda + gk)
            : (Ap1 + (size_t)(row0 + arow) * lda + (gk - Asplit));
        float4 v = *(const float4*)ap;
        float* dst = As + arow * 36 + gk;
        dst[0] = f2tf(v.x); dst[1] = f2tf(v.y); dst[2] = f2tf(v.z); dst[3] = f2tf(v.w);
    }
    #pragma unroll
    for (int h = 0; h < 4; ++h) {
        int rw = brow + h * 8;
        float4 v = *(const float4*)(W + (size_t)rw * N + col0 + bn4);
        float* dst = Bs + rw * 132 + bn4;
        dst[0] = f2tf(v.x); dst[1] = f2tf(v.y); dst[2] = f2tf(v.z); dst[3] = f2tf(v.w);
    }
    __syncthreads();

    int buf = 0;
    for (int kt = 0; ; ) {
        int ktn = kt + 32;
        bool more = ktn < K;
        float4 aN[2], bN[4];
        if (more) {
            #pragma unroll
            for (int h = 0; h < 2; ++h) {
                int gk = ktn + acol + h * 4;
                const float* ap = (gk < Asplit)
                    ? (Ap0 + (size_t)(row0 + arow) * lda + gk)
                    : (Ap1 + (size_t)(row0 + arow) * lda + (gk - Asplit));
                aN[h] = *(const float4*)ap;
            }
            #pragma unroll
            for (int h = 0; h < 4; ++h)
                bN[h] = *(const float4*)(W + (size_t)(ktn + brow + h * 8) * N + col0 + bn4);
        }
        const float* Ab = As + buf * 2304;
        const float* Bb = Bs + buf * 4224;
        #pragma unroll
        for (int ks = 0; ks < 32; ks += 8) {
            int kk = ks + j;
            float a[2][4];
            #pragma unroll
            for (int mi = 0; mi < 2; ++mi) {
                int rr = wm + mi * 16 + g;
                a[mi][0] = Ab[rr * 36 + kk];       a[mi][1] = Ab[(rr + 8) * 36 + kk];
                a[mi][2] = Ab[rr * 36 + kk + 4];   a[mi][3] = Ab[(rr + 8) * 36 + kk + 4];
            }
            #pragma unroll
            for (int ni = 0; ni < 4; ++ni) {
                int nn = wn + ni * 8 + g;
                float b0 = Bb[kk * 132 + nn], b1 = Bb[(kk + 4) * 132 + nn];
                mma8(acc[0][ni], a[0][0], a[0][1], a[0][2], a[0][3], b0, b1);
                mma8(acc[1][ni], a[1][0], a[1][1], a[1][2], a[1][3], b0, b1);
            }
        }
        if (!more) break;
        float* An = As + (buf ^ 1) * 2304;
        float* Bn = Bs + (buf ^ 1) * 4224;
        #pragma unroll
        for (int h = 0; h < 2; ++h) {
            float* dst = An + arow * 36 + acol + h * 4;
            dst[0] = f2tf(aN[h].x); dst[1] = f2tf(aN[h].y);
            dst[2] = f2tf(aN[h].z); dst[3] = f2tf(aN[h].w);
        }
        #pragma unroll
        for (int h = 0; h < 4; ++h) {
            float* dst = Bn + (brow + h * 8) * 132 + bn4;
            dst[0] = f2tf(bN[h].x); dst[1] = f2tf(bN[h].y);
            dst[2] = f2tf(bN[h].z); dst[3] = f2tf(bN[h].w);
        }
        __syncthreads();
        buf ^= 1; kt = ktn;
    }

    #pragma unroll
    for (int mi = 0; mi < 2; ++mi)
        #pragma unroll
        for (int ni = 0; ni < 4; ++ni) {
            int rr = row0 + wm + mi * 16 + g;
            int cc = col0 + wn + ni * 8 + 2 * j;
            float b0v = bias[cc], b1v = bias[cc + 1];
            float v0 = acc[mi][ni][0] + b0v, v1 = acc[mi][ni][1] + b1v;
            float v2 = acc[mi][ni][2] + b0v, v3 = acc[mi][ni][3] + b1v;
            if (doRelu) {
                v0 = fmaxf(v0, 0.f); v1 = fmaxf(v1, 0.f);
                v2 = fmaxf(v2, 0.f); v3 = fmaxf(v3, 0.f);
            }
            if (doRound) { v0 = f2tf(v0); v1 = f2tf(v1); v2 = f2tf(v2); v3 = f2tf(v3); }
            if (doPerm) {
                int c0p = dperm(cc), c1p = dperm(cc + 1);
                C[(size_t)rr * N + c0p] = v0; C[(size_t)rr * N + c1p] = v1;
                C[(size_t)(rr + 8) * N + c0p] = v2; C[(size_t)(rr + 8) * N + c1p] = v3;
            } else {
                *(float2*)(C + (size_t)rr * N + cc) = make_float2(v0, v1);
                *(float2*)(C + (size_t)(rr + 8) * N + cc) = make_float2(v2, v3);
            }
        }
}

// ---------- fused co-attention branch: permuted layout, no shuffles ----------
__global__ __launch_bounds__(256) void k_branch_tc()
{
    __shared__ float sK[2][64 * 20];
    __shared__ float sV[2][16 * 68];

    int eblk = blockIdx.x, b = blockIdx.y, r = blockIdx.z;
    int tid = threadIdx.x, lane = tid & 31, warp = tid >> 5;
    int g = lane >> 2, j = lane & 3;
    int ew = warp * 16;

    const float* gk  = g_K + (size_t)(r * 64 + b) * 16384;
    const float* gvb = g_V + (size_t)r * 655360 + (size_t)b * 10240;

    // J fragments (loop-invariant), direct LDG; g_J pre-rounded
    float jf[2][4];
    {
        int e0 = eblk * 128 + ew + g;
        const float* jb = g_J + (size_t)b * 20480;
        jf[0][0] = jb[(size_t)j * 2048 + e0];
        jf[0][1] = jb[(size_t)j * 2048 + e0 + 8];
        jf[0][2] = jb[(size_t)(j + 4) * 2048 + e0];
        jf[0][3] = jb[(size_t)(j + 4) * 2048 + e0 + 8];
        if (j < 2) {
            jf[1][0] = jb[(size_t)(8 + j) * 2048 + e0];
            jf[1][1] = jb[(size_t)(8 + j) * 2048 + e0 + 8];
        } else { jf[1][0] = 0.f; jf[1][1] = 0.f; }
        jf[1][2] = 0.f; jf[1][3] = 0.f;
    }

    // zero sV pad rows (t=10..15) in both buffers
    for (int i = tid; i < 2 * 6 * 68; i += 256) {
        int bb = i / 408, rem = i - bb * 408;
        sV[bb][(10 + rem / 68) * 68 + (rem % 68)] = 0.0f;
    }
    // stage chunk 0 (g_K rows already permuted; g_V cols already permuted)
    {
        int d = tid >> 2, k4 = (tid & 3) * 4;
        float4 kv = *(const float4*)(gk + (size_t)d * 16 + k4);
        *(float4*)&sK[0][d * 20 + k4] = kv;
        if (tid < 160) {
            int t = tid >> 4, d4 = (tid & 15) * 4;
            float4 vv = *(const float4*)(gvb + (size_t)t * 1024 + d4);
            *(float4*)&sV[0][t * 68 + d4] = vv;
        }
    }
    __syncthreads();

    float accW[2][4] = {};

    for (int ch = 0; ch < 16; ++ch) {
        float4 kreg = make_float4(0.f, 0.f, 0.f, 0.f);
        float4 vreg = make_float4(0.f, 0.f, 0.f, 0.f);
        bool more = (ch + 1) < 16;
        if (more) {
            int d = tid >> 2, k4 = (tid & 3) * 4;
            kreg = *(const float4*)(gk + (size_t)((ch + 1) * 64 + d) * 16 + k4);
            if (tid < 160) {
                int t = tid >> 4, d4 = (tid & 15) * 4;
                vreg = *(const float4*)(gvb + (size_t)t * 1024 + (ch + 1) * 64 + d4);
            }
        }
        const float* Kb = sK[ch & 1];
        const float* Vb = sV[ch & 1];

        // GEMM1: accS[e16][d64], k = t(16), A from registers
        float accS[8][4] = {};
        #pragma unroll
        for (int s = 0; s < 2; ++s) {
            int kk = s * 8 + j;
            #pragma unroll
            for (int ni = 0; ni < 8; ++ni) {
                int dd = ni * 8 + g;
                mma8(accS[ni], jf[s][0], jf[s][1], jf[s][2], jf[s][3],
                     Kb[dd * 20 + kk], Kb[dd * 20 + kk + 4]);
            }
        }
        // tanh -> direct A-fragment (permutation makes layouts match), GEMM2
        #pragma unroll
        for (int ni = 0; ni < 8; ++ni) {
            float a0 = f2tf(tanhx(accS[ni][0]));   // (e=g,   phys d=j)
            float a1 = f2tf(tanhx(accS[ni][2]));   // (e=g+8, phys d=j)
            float a2 = f2tf(tanhx(accS[ni][1]));   // (e=g,   phys d=j+4)
            float a3 = f2tf(tanhx(accS[ni][3]));   // (e=g+8, phys d=j+4)
            #pragma unroll
            for (int nt = 0; nt < 2; ++nt) {
                float2 bv = *(const float2*)&Vb[(nt * 8 + g) * 68 + ni * 8 + 2 * j];
                mma8(accW[nt], a0, a1, a2, a3, bv.x, bv.y);
            }
        }
        if (more) {
            int d = tid >> 2, k4 = (tid & 3) * 4;
            *(float4*)&sK[(ch + 1) & 1][d * 20 + k4] = kreg;
            if (tid < 160) {
                int t = tid >> 4, d4 = (tid & 15) * 4;
                *(float4*)&sV[(ch + 1) & 1][t * 68 + d4] = vreg;
            }
            __syncthreads();
        }
    }

    // epilogue: g_O[(r*640+b*10+t)][e] = relu(tanh(accW))
    int e = eblk * 128 + ew + g;
    #pragma unroll
    for (int nt = 0; nt < 2; ++nt) {
        #pragma unroll
        for (int jj = 0; jj < 2; ++jj) {
            int t = nt * 8 + 2 * j + jj;
            if (t < 10) {
                size_t rowoff = ((size_t)r * 640 + b * 10 + t) * 2048;
                g_O[rowoff + e]     = fmaxf(tanhx(accW[nt][jj]), 0.0f);
                g_O[rowoff + e + 8] = fmaxf(tanhx(accW[nt][2 + jj]), 0.0f);
            }
        }
    }
}

// ---------- final: out = audio + video + fuse1 + fuse2 (float4) ----------
__global__ __launch_bounds__(256) void k_final(
    const float* __restrict__ audio, const float* __restrict__ video,
    float* __restrict__ out)
{
    int i = blockIdx.x * 256 + threadIdx.x;
    float4 a = ((const float4*)audio)[i];
    float4 v = ((const float4*)video)[i];
    float4 f1 = ((const float4*)g_F)[i];
    float4 f2 = ((const float4*)(g_F + 655360))[i];
    float4 o;
    o.x = a.x + v.x + f1.x + f2.x;
    o.y = a.y + v.y + f1.y + f2.y;
    o.z = a.z + v.z + f1.z + f2.z;
    o.w = a.w + v.w + f1.w + f2.w;
    ((float4*)out)[i] = o;
}

extern "C" void kernel_launch(void* const* d_in, const int* in_sizes, int n_in,
                              void* d_out, int out_size)
{
    const float* audio = (const float*)d_in[0];
    const float* video = (const float*)d_in[1];
    const float* Wq  = (const float*)d_in[2];
    const float* bq  = (const float*)d_in[3];
    const float* Wk1 = (const float*)d_in[4];
    const float* bk1 = (const float*)d_in[5];
    const float* Wk2 = (const float*)d_in[6];
    const float* bk2 = (const float*)d_in[7];
    const float* Wv1 = (const float*)d_in[8];
    const float* bv1 = (const float*)d_in[9];
    const float* Wv2 = (const float*)d_in[10];
    const float* bv2 = (const float*)d_in[11];
    const float* Wf  = (const float*)d_in[12];
    const float* bf  = (const float*)d_in[13];
    float* out = (float*)d_out;

    static int smemSet = 0;
    if (!smemSet) {
        cudaFuncSetAttribute(k_gemm_tc, cudaFuncAttributeMaxDynamicSharedMemorySize, 52224);
        smemSet = 1;
    }

    k_key<<<dim3(64, 2), 256>>>(audio, video, Wk1, bk1, Wk2, bk2);
    // joint = concat(audio,video) @ Wq + bq  [640x2048] K=2048, rounded
    k_gemm_tc<<<dim3(16, 10), 256, 52224>>>(audio, video, audio, video, -1, 1024, 1024,
                                            Wq, Wq, bq, bq, 0, 0, 640, 2048, 2048, 0, 1, 0);
    // val1/val2 batched over z  [640x1024] K=1024, rounded + d-permuted
    k_gemm_tc<<<dim3(8, 10, 2), 256, 52224>>>(audio, audio, video, video, -1, 1024, 1024,
                                              Wv1, Wv2, bv1, bv2, 1, (size_t)640 * 1024,
                                              640, 1024, 1024, 0, 1, 1);
    // fused co-attention branches
    k_branch_tc<<<dim3(16, 64, 2), 256>>>();
    // fuse = relu(g_O @ Wf + bf)  [1280x1024] K=2048
    k_gemm_tc<<<dim3(8, 20), 256, 52224>>>(nullptr, nullptr, nullptr, nullptr, 3, 2048, 2048,
                                           Wf, Wf, bf, bf, 4, 0, 1280, 1024, 2048, 1, 0, 0);
    k_final<<<640, 256>>>(audio, video, out);
}

// round 6
// speedup vs baseline: 2.8077x; 1.1723x over previous
#include <cuda_runtime.h>
#include <cstdint>

#define DINL __device__ __forceinline__
#define SCALE_F 0.022097086912079608f  // 1/sqrt(2048)

// ---------- scratch ----------
__device__ float g_J[640 * 2048];            // joint, tf32-rounded
__device__ float g_K[2 * 64 * 1024 * 16];    // keys, SCALE folded, tf32, d-rows PERMUTED
__device__ float g_V[2 * 640 * 1024];        // values, tf32, d-cols PERMUTED
__device__ float g_O[2 * 640 * 2048];        // relu(tanh(weighted)), tf32-rounded
__device__ float g_F[1280 * 1024];           // fc_fusion out
__device__ float g_W[9699328];               // pre-rounded: [audio|video|Wq|Wv1|Wv2|Wf]

// float offsets into g_W
#define OW_A   0
#define OW_V   655360
#define OW_WQ  1310720
#define OW_WV1 5505024
#define OW_WV2 6553600
#define OW_WF  7602176

DINL float tanhx(float x) {
    float y; asm("tanh.approx.f32 %0, %1;" : "=f"(y) : "f"(x)); return y;
}
DINL float f2tf(float x) {
    uint32_t r; asm("cvt.rna.tf32.f32 %0, %1;" : "=r"(r) : "f"(x));
    return __uint_as_float(r);
}
DINL void mma8(float* c, float a0, float a1, float a2, float a3, float b0, float b1) {
    asm volatile(
        "mma.sync.aligned.m16n8k8.row.col.f32.tf32.tf32.f32 "
        "{%0,%1,%2,%3},{%4,%5,%6,%7},{%8,%9},{%0,%1,%2,%3};"
        : "+f"(c[0]), "+f"(c[1]), "+f"(c[2]), "+f"(c[3])
        : "r"(__float_as_uint(a0)), "r"(__float_as_uint(a1)),
          "r"(__float_as_uint(a2)), "r"(__float_as_uint(a3)),
          "r"(__float_as_uint(b0)), "r"(__float_as_uint(b1)));
}
DINL int dperm(int c) {  // storage position of physical in-group index
    return (c & ~7) + 2 * (c & 3) + ((c & 7) >> 2);
}
DINL float* bufptr(int sel) {
    switch (sel) {
        case 0: return g_J;
        case 1: return g_V;
        case 3: return g_O;
        default: return g_F;
    }
}
DINL void cpa16(uint32_t dst, const void* src) {
    asm volatile("cp.async.cg.shared.global [%0], [%1], 16;\n" :: "r"(dst), "l"(src));
}
DINL void cpa_commit() { asm volatile("cp.async.commit_group;\n" ::: "memory"); }
template<int W> DINL void cpa_wait() {
    asm volatile("cp.async.wait_group %0;\n" :: "n"(W) : "memory");
}

// ---------- pre-round inputs + weights into g_W ----------
__global__ __launch_bounds__(256) void k_round(
    const float* __restrict__ a, const float* __restrict__ v,
    const float* __restrict__ wq, const float* __restrict__ wv1,
    const float* __restrict__ wv2, const float* __restrict__ wf)
{
    int i = blockIdx.x * 256 + threadIdx.x;     // float4 index
    const float4* src; int base;
    if      (i <  163840) { src = (const float4*)a;   base = 0; }
    else if (i <  327680) { src = (const float4*)v;   base = 163840; }
    else if (i < 1376256) { src = (const float4*)wq;  base = 327680; }
    else if (i < 1638400) { src = (const float4*)wv1; base = 1376256; }
    else if (i < 1900544) { src = (const float4*)wv2; base = 1638400; }
    else                  { src = (const float4*)wf;  base = 1900544; }
    float4 x = src[i - base];
    x.x = f2tf(x.x); x.y = f2tf(x.y); x.z = f2tf(x.z); x.w = f2tf(x.w);
    ((float4*)g_W)[i] = x;
}

// ---------- key linears: permuted rows ----------
__global__ __launch_bounds__(256) void k_key(
    const float* __restrict__ audio, const float* __restrict__ video,
    const float* __restrict__ Wk1, const float* __restrict__ bk1,
    const float* __restrict__ Wk2, const float* __restrict__ bk2)
{
    int b = blockIdx.x, r = blockIdx.y;
    const float* X  = r ? video : audio;
    const float* Wk = r ? Wk2 : Wk1;
    const float* bk = r ? bk2 : bk1;
    __shared__ float sW[100], sb[10];
    if (threadIdx.x < 100) sW[threadIdx.x] = Wk[threadIdx.x];
    if (threadIdx.x < 10)  sb[threadIdx.x] = bk[threadIdx.x];
    __syncthreads();
    const float* xb = X + (size_t)b * 10240;
    float* kout = g_K + (size_t)(r * 64 + b) * 16384;
    for (int d = threadIdx.x; d < 1024; d += 256) {
        float a[10];
        #pragma unroll
        for (int t = 0; t < 10; ++t) a[t] = xb[t * 1024 + d];
        float* krow = kout + (size_t)dperm(d) * 16;
        #pragma unroll
        for (int t = 10; t < 16; ++t) krow[t] = 0.0f;
        #pragma unroll
        for (int t = 0; t < 10; ++t) {
            float s = sb[t];
            #pragma unroll
            for (int tp = 0; tp < 10; ++tp) s += a[tp] * sW[tp * 10 + t];
            krow[t] = f2tf(s * SCALE_F);
        }
    }
}

// ---------- tf32 GEMM: BM=64 BN=128 BK=32, 4-stage cp.async ----------
// stage layout (floats): A[64*36]=2304 then B[32*132]=4224 -> 6528/stage
__global__ __launch_bounds__(256) void k_gemm_tc(
    const float* A0, const float* A1, const float* A0z, const float* A1z,
    int aSel, int Asplit, int lda,
    const float* W0, const float* W1, const float* bias0, const float* bias1,
    int cSel, size_t cStride, int M, int N, int K,
    int doRelu, int doRound, int doPerm)
{
    extern __shared__ float smg[];
    uint32_t sb32 = (uint32_t)__cvta_generic_to_shared(smg);
    int z = blockIdx.z;
    const float* Ap0, *Ap1;
    if (aSel < 0) { Ap0 = z ? A0z : A0; Ap1 = z ? A1z : A1; }
    else          { Ap0 = Ap1 = bufptr(aSel); }
    const float* W    = z ? W1 : W0;
    const float* bias = z ? bias1 : bias0;
    float* C = bufptr(cSel) + (size_t)z * cStride;

    int tid = threadIdx.x, lane = tid & 31, warp = tid >> 5;
    int g = lane >> 2, j = lane & 3;
    int wm = (warp >> 2) * 32, wn = (warp & 3) * 32;
    int row0 = blockIdx.y * 64, col0 = blockIdx.x * 128;
    float acc[2][4][4] = {};

    int nt = K >> 5;

    // issue lambda-ish via macro
    #define GEMM_ISSUE(TI, ST) do {                                             \
        int kb_ = (TI) << 5;                                                    \
        uint32_t sA_ = sb32 + (uint32_t)(ST) * 6528u * 4u;                      \
        uint32_t sB_ = sA_ + 2304u * 4u;                                        \
        _Pragma("unroll")                                                       \
        for (int h_ = 0; h_ < 2; ++h_) {                                        \
            int c_ = h_ * 256 + tid;                                            \
            int ar_ = c_ >> 3, kg_ = (c_ & 7) * 4;                              \
            int gk_ = kb_ + kg_;                                                \
            const float* ap_ = (gk_ < Asplit)                                   \
                ? (Ap0 + (size_t)(row0 + ar_) * lda + gk_)                      \
                : (Ap1 + (size_t)(row0 + ar_) * lda + (gk_ - Asplit));          \
            cpa16(sA_ + (uint32_t)(ar_ * 36 + kg_) * 4u, ap_);                  \
        }                                                                       \
        _Pragma("unroll")                                                       \
        for (int h_ = 0; h_ < 4; ++h_) {                                        \
            int c_ = h_ * 256 + tid;                                            \
            int br_ = c_ >> 5, cg_ = (c_ & 31) * 4;                             \
            cpa16(sB_ + (uint32_t)(br_ * 132 + cg_) * 4u,                       \
                  W + (size_t)(kb_ + br_) * N + col0 + cg_);                    \
        }                                                                       \
    } while (0)

    // prologue: tiles 0..2
    if (0 < nt) { GEMM_ISSUE(0, 0); } cpa_commit();
    if (1 < nt) { GEMM_ISSUE(1, 1); } cpa_commit();
    if (2 < nt) { GEMM_ISSUE(2, 2); } cpa_commit();

    for (int ti = 0; ti < nt; ++ti) {
        cpa_wait<2>();
        __syncthreads();
        int tin = ti + 3;
        if (tin < nt) { GEMM_ISSUE(tin, tin & 3); }
        cpa_commit();

        const float* Ab = smg + (ti & 3) * 6528;
        const float* Bb = Ab + 2304;
        #pragma unroll
        for (int ks = 0; ks < 32; ks += 8) {
            int kk = ks + j;
            float a[2][4];
            #pragma unroll
            for (int mi = 0; mi < 2; ++mi) {
                int rr = wm + mi * 16 + g;
                a[mi][0] = Ab[rr * 36 + kk];       a[mi][1] = Ab[(rr + 8) * 36 + kk];
                a[mi][2] = Ab[rr * 36 + kk + 4];   a[mi][3] = Ab[(rr + 8) * 36 + kk + 4];
            }
            #pragma unroll
            for (int ni = 0; ni < 4; ++ni) {
                int nn = wn + ni * 8 + g;
                float b0 = Bb[kk * 132 + nn], b1 = Bb[(kk + 4) * 132 + nn];
                mma8(acc[0][ni], a[0][0], a[0][1], a[0][2], a[0][3], b0, b1);
                mma8(acc[1][ni], a[1][0], a[1][1], a[1][2], a[1][3], b0, b1);
            }
        }
    }
    #undef GEMM_ISSUE

    #pragma unroll
    for (int mi = 0; mi < 2; ++mi)
        #pragma unroll
        for (int ni = 0; ni < 4; ++ni) {
            int rr = row0 + wm + mi * 16 + g;
            int cc = col0 + wn + ni * 8 + 2 * j;
            float b0v = bias[cc], b1v = bias[cc + 1];
            float v0 = acc[mi][ni][0] + b0v, v1 = acc[mi][ni][1] + b1v;
            float v2 = acc[mi][ni][2] + b0v, v3 = acc[mi][ni][3] + b1v;
            if (doRelu) {
                v0 = fmaxf(v0, 0.f); v1 = fmaxf(v1, 0.f);
                v2 = fmaxf(v2, 0.f); v3 = fmaxf(v3, 0.f);
            }
            if (doRound) { v0 = f2tf(v0); v1 = f2tf(v1); v2 = f2tf(v2); v3 = f2tf(v3); }
            if (doPerm) {
                int c0p = dperm(cc), c1p = dperm(cc + 1);
                C[(size_t)rr * N + c0p] = v0; C[(size_t)rr * N + c1p] = v1;
                C[(size_t)(rr + 8) * N + c0p] = v2; C[(size_t)(rr + 8) * N + c1p] = v3;
            } else {
                *(float2*)(C + (size_t)rr * N + cc) = make_float2(v0, v1);
                *(float2*)(C + (size_t)(rr + 8) * N + cc) = make_float2(v2, v3);
            }
        }
}

// ---------- fused co-attention branch: 2 e-tiles/warp, cp.async 3-stage ----------
// stage layout (floats): K[64*20]=1280 then V[16*68]=1088 -> 2368/stage, 3 stages
__global__ __launch_bounds__(256, 2) void k_branch_tc()
{
    __shared__ float sm[3 * 2368];
    uint32_t sb32 = (uint32_t)__cvta_generic_to_shared(sm);

    int eblk = blockIdx.x, b = blockIdx.y, r = blockIdx.z;
    int tid = threadIdx.x, lane = tid & 31, warp = tid >> 5;
    int g = lane >> 2, j = lane & 3;

    const float* gk  = g_K + (size_t)(r * 64 + b) * 16384;
    const float* gvb = g_V + (size_t)r * 655360 + (size_t)b * 10240;

    // J fragments for both e-tiles (loop-invariant); g_J pre-rounded
    float jf[2][2][4];
    {
        const float* jb = g_J + (size_t)b * 20480;
        int e0 = eblk * 256 + warp * 32 + g;
        #pragma unroll
        for (int tile = 0; tile < 2; ++tile) {
            int eT = e0 + tile * 16;
            jf[tile][0][0] = jb[(size_t)j * 2048 + eT];
            jf[tile][0][1] = jb[(size_t)j * 2048 + eT + 8];
            jf[tile][0][2] = jb[(size_t)(j + 4) * 2048 + eT];
            jf[tile][0][3] = jb[(size_t)(j + 4) * 2048 + eT + 8];
            jf[tile][1][0] = (j < 2) ? jb[(size_t)(8 + j) * 2048 + eT] : 0.f;
            jf[tile][1][1] = (j < 2) ? jb[(size_t)(8 + j) * 2048 + eT + 8] : 0.f;
            jf[tile][1][2] = 0.f; jf[tile][1][3] = 0.f;
        }
    }

    // zero V pad rows (t=10..15) in all stages (cp.async never writes them)
    for (int i = tid; i < 3 * 6 * 68; i += 256) {
        int st = i / 408, rem = i - st * 408;
        sm[st * 2368 + 1280 + (10 + rem / 68) * 68 + (rem % 68)] = 0.0f;
    }

    #define BR_ISSUE(CH, ST) do {                                               \
        uint32_t kb_ = sb32 + (uint32_t)(ST) * 2368u * 4u;                      \
        int d_ = tid >> 2, k4_ = (tid & 3) * 4;                                 \
        cpa16(kb_ + (uint32_t)(d_ * 20 + k4_) * 4u,                             \
              gk + (size_t)((CH) * 64 + d_) * 16 + k4_);                        \
        if (tid < 160) {                                                        \
            int t_ = tid >> 4, d4_ = (tid & 15) * 4;                            \
            cpa16(kb_ + (uint32_t)(1280 + t_ * 68 + d4_) * 4u,                  \
                  gvb + (size_t)t_ * 1024 + (CH) * 64 + d4_);                   \
        }                                                                       \
    } while (0)

    BR_ISSUE(0, 0); cpa_commit();
    BR_ISSUE(1, 1); cpa_commit();

    float accW[2][2][4] = {};

    for (int ch = 0; ch < 16; ++ch) {
        cpa_wait<1>();
        __syncthreads();
        if (ch + 2 < 16) { BR_ISSUE(ch + 2, (ch + 2) % 3); }
        cpa_commit();

        const float* Kb = sm + (ch % 3) * 2368;
        const float* Vb = Kb + 1280;

        #pragma unroll
        for (int dh = 0; dh < 2; ++dh) {
            float accS[2][4][4] = {};
            // GEMM1: both tiles share B (K)
            #pragma unroll
            for (int s = 0; s < 2; ++s) {
                int kk = s * 8 + j;
                #pragma unroll
                for (int ni = 0; ni < 4; ++ni) {
                    int dd = dh * 32 + ni * 8 + g;
                    float b0 = Kb[dd * 20 + kk], b1 = Kb[dd * 20 + kk + 4];
                    mma8(accS[0][ni], jf[0][s][0], jf[0][s][1], jf[0][s][2], jf[0][s][3], b0, b1);
                    mma8(accS[1][ni], jf[1][s][0], jf[1][s][1], jf[1][s][2], jf[1][s][3], b0, b1);
                }
            }
            // tanh -> A-fragment (permuted layout), GEMM2: both tiles share B (V)
            #pragma unroll
            for (int ni = 0; ni < 4; ++ni) {
                float a0A = f2tf(tanhx(accS[0][ni][0]));
                float a1A = f2tf(tanhx(accS[0][ni][2]));
                float a2A = f2tf(tanhx(accS[0][ni][1]));
                float a3A = f2tf(tanhx(accS[0][ni][3]));
                float a0B = f2tf(tanhx(accS[1][ni][0]));
                float a1B = f2tf(tanhx(accS[1][ni][2]));
                float a2B = f2tf(tanhx(accS[1][ni][1]));
                float a3B = f2tf(tanhx(accS[1][ni][3]));
                #pragma unroll
                for (int nt = 0; nt < 2; ++nt) {
                    float2 bv = *(const float2*)&Vb[(nt * 8 + g) * 68 + dh * 32 + ni * 8 + 2 * j];
                    mma8(accW[0][nt], a0A, a1A, a2A, a3A, bv.x, bv.y);
                    mma8(accW[1][nt], a0B, a1B, a2B, a3B, bv.x, bv.y);
                }
            }
        }
    }
    #undef BR_ISSUE

    // epilogue: g_O = tf32(relu(tanh(accW)))
    #pragma unroll
    for (int tile = 0; tile < 2; ++tile) {
        int e = eblk * 256 + warp * 32 + tile * 16 + g;
        #pragma unroll
        for (int nt = 0; nt < 2; ++nt) {
            #pragma unroll
            for (int jj = 0; jj < 2; ++jj) {
                int t = nt * 8 + 2 * j + jj;
                if (t < 10) {
                    size_t rowoff = ((size_t)r * 640 + b * 10 + t) * 2048;
                    g_O[rowoff + e]     = f2tf(fmaxf(tanhx(accW[tile][nt][jj]), 0.0f));
                    g_O[rowoff + e + 8] = f2tf(fmaxf(tanhx(accW[tile][nt][2 + jj]), 0.0f));
                }
            }
        }
    }
}

// ---------- final: out = audio + video + fuse1 + fuse2 (float4) ----------
__global__ __launch_bounds__(256) void k_final(
    const float* __restrict__ audio, const float* __restrict__ video,
    float* __restrict__ out)
{
    int i = blockIdx.x * 256 + threadIdx.x;
    float4 a = ((const float4*)audio)[i];
    float4 v = ((const float4*)video)[i];
    float4 f1 = ((const float4*)g_F)[i];
    float4 f2 = ((const float4*)(g_F + 655360))[i];
    float4 o;
    o.x = a.x + v.x + f1.x + f2.x;
    o.y = a.y + v.y + f1.y + f2.y;
    o.z = a.z + v.z + f1.z + f2.z;
    o.w = a.w + v.w + f1.w + f2.w;
    ((float4*)out)[i] = o;
}

extern "C" void kernel_launch(void* const* d_in, const int* in_sizes, int n_in,
                              void* d_out, int out_size)
{
    const float* audio = (const float*)d_in[0];
    const float* video = (const float*)d_in[1];
    const float* Wq  = (const float*)d_in[2];
    const float* bq  = (const float*)d_in[3];
    const float* Wk1 = (const float*)d_in[4];
    const float* bk1 = (const float*)d_in[5];
    const float* Wk2 = (const float*)d_in[6];
    const float* bk2 = (const float*)d_in[7];
    const float* Wv1 = (const float*)d_in[8];
    const float* bv1 = (const float*)d_in[9];
    const float* Wv2 = (const float*)d_in[10];
    const float* bv2 = (const float*)d_in[11];
    const float* Wf  = (const float*)d_in[12];
    const float* bf  = (const float*)d_in[13];
    float* out = (float*)d_out;

    static float* wb = nullptr;
    if (!wb) {
        cudaGetSymbolAddress((void**)&wb, g_W);
        cudaFuncSetAttribute(k_gemm_tc, cudaFuncAttributeMaxDynamicSharedMemorySize, 104448);
    }

    // pre-round inputs + weights (tf32 RNA)
    k_round<<<9472, 256>>>(audio, video, Wq, Wv1, Wv2, Wf);
    // key linears (tiny, uses raw inputs)
    k_key<<<dim3(64, 2), 256>>>(audio, video, Wk1, bk1, Wk2, bk2);
    // joint = concat(audio,video) @ Wq + bq  [640x2048] K=2048 -> g_J (rounded)
    k_gemm_tc<<<dim3(16, 10), 256, 104448>>>(
        wb + OW_A, wb + OW_V, wb + OW_A, wb + OW_V, -1, 1024, 1024,
        wb + OW_WQ, wb + OW_WQ, bq, bq, 0, 0, 640, 2048, 2048, 0, 1, 0);
    // val1/val2 (z)  [640x1024] K=1024 -> g_V (rounded + d-permuted)
    k_gemm_tc<<<dim3(8, 10, 2), 256, 104448>>>(
        wb + OW_A, wb + OW_A, wb + OW_V, wb + OW_V, -1, 1024, 1024,
        wb + OW_WV1, wb + OW_WV2, bv1, bv2, 1, (size_t)640 * 1024,
        640, 1024, 1024, 0, 1, 1);
    // fused co-attention branches (2 e-tiles/warp)
    k_branch_tc<<<dim3(8, 64, 2), 256>>>();
    // fuse = relu(g_O @ Wf + bf)  [1280x1024] K=2048 -> g_F
    k_gemm_tc<<<dim3(8, 20), 256, 104448>>>(
        nullptr, nullptr, nullptr, nullptr, 3, 2048, 2048,
        wb + OW_WF, wb + OW_WF, bf, bf, 4, 0, 1280, 1024, 2048, 1, 0, 0);
    k_final<<<640, 256>>>(audio, video, out);
}

// round 8
// speedup vs baseline: 2.9740x; 1.0593x over previous
#include <cuda_runtime.h>
#include <cstdint>

#define DINL __device__ __forceinline__
#define SCALE_F 0.022097086912079608f  // 1/sqrt(2048)

// ---------- scratch ----------
__device__ float g_J[640 * 2048];            // joint, tf32-rounded
__device__ float g_K[2 * 64 * 1024 * 16];    // keys, SCALE folded, tf32, d-rows PERMUTED
__device__ float g_V[2 * 640 * 1024];        // values, tf32, d-cols PERMUTED
__device__ float g_O[2 * 640 * 2048];        // relu(tanh(weighted)), tf32-rounded
__device__ float g_F[1280 * 1024];           // fc_fusion out
__device__ float g_W[9699328];               // pre-rounded: [audio|video|Wq|Wv1|Wv2|Wf]

// float offsets into g_W
#define OW_A   0
#define OW_V   655360
#define OW_WQ  1310720
#define OW_WV1 5505024
#define OW_WV2 6553600
#define OW_WF  7602176

DINL float tanhx(float x) {
    float y; asm("tanh.approx.f32 %0, %1;" : "=f"(y) : "f"(x)); return y;
}
DINL float f2tf(float x) {
    uint32_t r; asm("cvt.rna.tf32.f32 %0, %1;" : "=r"(r) : "f"(x));
    return __uint_as_float(r);
}
DINL void mma8(float* c, float a0, float a1, float a2, float a3, float b0, float b1) {
    asm volatile(
        "mma.sync.aligned.m16n8k8.row.col.f32.tf32.tf32.f32 "
        "{%0,%1,%2,%3},{%4,%5,%6,%7},{%8,%9},{%0,%1,%2,%3};"
        : "+f"(c[0]), "+f"(c[1]), "+f"(c[2]), "+f"(c[3])
        : "r"(__float_as_uint(a0)), "r"(__float_as_uint(a1)),
          "r"(__float_as_uint(a2)), "r"(__float_as_uint(a3)),
          "r"(__float_as_uint(b0)), "r"(__float_as_uint(b1)));
}
DINL int dperm(int c) {  // storage position of physical in-group index
    return (c & ~7) + 2 * (c & 3) + ((c & 7) >> 2);
}
DINL float* bufptr(int sel) {
    switch (sel) {
        case 0: return g_J;
        case 1: return g_V;
        case 3: return g_O;
        default: return g_F;
    }
}
DINL void cpa16(uint32_t dst, const void* src) {
    asm volatile("cp.async.cg.shared.global [%0], [%1], 16;\n" :: "r"(dst), "l"(src));
}
DINL void cpa_commit() { asm volatile("cp.async.commit_group;\n" ::: "memory"); }
template<int W> DINL void cpa_wait() {
    asm volatile("cp.async.wait_group %0;\n" :: "n"(W) : "memory");
}

// ---------- pre-round inputs + weights into g_W ----------
__global__ __launch_bounds__(256) void k_round(
    const float* __restrict__ a, const float* __restrict__ v,
    const float* __restrict__ wq, const float* __restrict__ wv1,
    const float* __restrict__ wv2, const float* __restrict__ wf)
{
    int i = blockIdx.x * 256 + threadIdx.x;     // float4 index
    const float4* src; int base;
    if      (i <  163840) { src = (const float4*)a;   base = 0; }
    else if (i <  327680) { src = (const float4*)v;   base = 163840; }
    else if (i < 1376256) { src = (const float4*)wq;  base = 327680; }
    else if (i < 1638400) { src = (const float4*)wv1; base = 1376256; }
    else if (i < 1900544) { src = (const float4*)wv2; base = 1638400; }
    else                  { src = (const float4*)wf;  base = 1900544; }
    float4 x = src[i - base];
    x.x = f2tf(x.x); x.y = f2tf(x.y); x.z = f2tf(x.z); x.w = f2tf(x.w);
    ((float4*)g_W)[i] = x;
}

// ---------- key linears: permuted rows ----------
__global__ __launch_bounds__(256) void k_key(
    const float* __restrict__ audio, const float* __restrict__ video,
    const float* __restrict__ Wk1, const float* __restrict__ bk1,
    const float* __restrict__ Wk2, const float* __restrict__ bk2)
{
    int b = blockIdx.x, r = blockIdx.y;
    const float* X  = r ? video : audio;
    const float* Wk = r ? Wk2 : Wk1;
    const float* bk = r ? bk2 : bk1;
    __shared__ float sW[100], sb[10];
    if (threadIdx.x < 100) sW[threadIdx.x] = Wk[threadIdx.x];
    if (threadIdx.x < 10)  sb[threadIdx.x] = bk[threadIdx.x];
    __syncthreads();
    const float* xb = X + (size_t)b * 10240;
    float* kout = g_K + (size_t)(r * 64 + b) * 16384;
    for (int d = threadIdx.x; d < 1024; d += 256) {
        float a[10];
        #pragma unroll
        for (int t = 0; t < 10; ++t) a[t] = xb[t * 1024 + d];
        float* krow = kout + (size_t)dperm(d) * 16;
        #pragma unroll
        for (int t = 10; t < 16; ++t) krow[t] = 0.0f;
        #pragma unroll
        for (int t = 0; t < 10; ++t) {
            float s = sb[t];
            #pragma unroll
            for (int tp = 0; tp < 10; ++tp) s += a[tp] * sW[tp * 10 + t];
            krow[t] = f2tf(s * SCALE_F);
        }
    }
}

// ---------- tf32 GEMM: BM=64 BN=64 BK=32, 3-stage cp.async ----------
// stage layout (floats): A[64*36]=2304 then B[32*68]=2176 -> 4480/stage, 3 stages
__global__ __launch_bounds__(256) void k_gemm_tc(
    const float* A0, const float* A1, const float* A0z, const float* A1z,
    int aSel, int Asplit, int lda,
    const float* W0, const float* W1, const float* bias0, const float* bias1,
    int cSel, size_t cStride, int M, int N, int K,
    int doRelu, int doRound, int doPerm)
{
    extern __shared__ float smg[];
    uint32_t sb32 = (uint32_t)__cvta_generic_to_shared(smg);
    int z = blockIdx.z;
    const float* Ap0, *Ap1;
    if (aSel < 0) { Ap0 = z ? A0z : A0; Ap1 = z ? A1z : A1; }
    else          { Ap0 = Ap1 = bufptr(aSel); }
    const float* W    = z ? W1 : W0;
    const float* bias = z ? bias1 : bias0;
    float* C = bufptr(cSel) + (size_t)z * cStride;

    int tid = threadIdx.x, lane = tid & 31, warp = tid >> 5;
    int g = lane >> 2, j = lane & 3;
    int wm = (warp >> 2) * 32, wn = (warp & 3) * 16;
    int row0 = blockIdx.y * 64, col0 = blockIdx.x * 64;
    float acc[2][2][4] = {};

    int nt = K >> 5;

    #define GEMM_ISSUE(TI, ST) do {                                             \
        int kb_ = (TI) << 5;                                                    \
        uint32_t sA_ = sb32 + (uint32_t)(ST) * 4480u * 4u;                      \
        uint32_t sB_ = sA_ + 2304u * 4u;                                        \
        _Pragma("unroll")                                                       \
        for (int h_ = 0; h_ < 2; ++h_) {                                        \
            int c_ = h_ * 256 + tid;                                            \
            int ar_ = c_ >> 3, kg_ = (c_ & 7) * 4;                              \
            int gk_ = kb_ + kg_;                                                \
            const float* ap_ = (gk_ < Asplit)                                   \
                ? (Ap0 + (size_t)(row0 + ar_) * lda + gk_)                      \
                : (Ap1 + (size_t)(row0 + ar_) * lda + (gk_ - Asplit));          \
            cpa16(sA_ + (uint32_t)(ar_ * 36 + kg_) * 4u, ap_);                  \
        }                                                                       \
        _Pragma("unroll")                                                       \
        for (int h_ = 0; h_ < 2; ++h_) {                                        \
            int c_ = h_ * 256 + tid;                                            \
            int br_ = c_ >> 4, cg_ = (c_ & 15) * 4;                             \
            cpa16(sB_ + (uint32_t)(br_ * 68 + cg_) * 4u,                        \
                  W + (size_t)(kb_ + br_) * N + col0 + cg_);                    \
        }                                                                       \
    } while (0)

    // prologue: tiles 0,1
    if (0 < nt) { GEMM_ISSUE(0, 0); } cpa_commit();
    if (1 < nt) { GEMM_ISSUE(1, 1); } cpa_commit();

    for (int ti = 0; ti < nt; ++ti) {
        cpa_wait<1>();
        __syncthreads();
        int tin = ti + 2;
        if (tin < nt) { GEMM_ISSUE(tin, tin % 3); }
        cpa_commit();

        const float* Ab = smg + (ti % 3) * 4480;
        const float* Bb = Ab + 2304;
        #pragma unroll
        for (int ks = 0; ks < 32; ks += 8) {
            int kk = ks + j;
            float a[2][4];
            #pragma unroll
            for (int mi = 0; mi < 2; ++mi) {
                int rr = wm + mi * 16 + g;
                a[mi][0] = Ab[rr * 36 + kk];       a[mi][1] = Ab[(rr + 8) * 36 + kk];
                a[mi][2] = Ab[rr * 36 + kk + 4];   a[mi][3] = Ab[(rr + 8) * 36 + kk + 4];
            }
            #pragma unroll
            for (int ni = 0; ni < 2; ++ni) {
                int nn = wn + ni * 8 + g;
                float b0 = Bb[kk * 68 + nn], b1 = Bb[(kk + 4) * 68 + nn];
                mma8(acc[0][ni], a[0][0], a[0][1], a[0][2], a[0][3], b0, b1);
                mma8(acc[1][ni], a[1][0], a[1][1], a[1][2], a[1][3], b0, b1);
            }
        }
        __syncthreads();
    }
    #undef GEMM_ISSUE

    #pragma unroll
    for (int mi = 0; mi < 2; ++mi)
        #pragma unroll
        for (int ni = 0; ni < 2; ++ni) {
            int rr = row0 + wm + mi * 16 + g;
            int cc = col0 + wn + ni * 8 + 2 * j;
            float b0v = bias[cc], b1v = bias[cc + 1];
            float v0 = acc[mi][ni][0] + b0v, v1 = acc[mi][ni][1] + b1v;
            float v2 = acc[mi][ni][2] + b0v, v3 = acc[mi][ni][3] + b1v;
            if (doRelu) {
                v0 = fmaxf(v0, 0.f); v1 = fmaxf(v1, 0.f);
                v2 = fmaxf(v2, 0.f); v3 = fmaxf(v3, 0.f);
            }
            if (doRound) { v0 = f2tf(v0); v1 = f2tf(v1); v2 = f2tf(v2); v3 = f2tf(v3); }
            if (doPerm) {
                int c0p = dperm(cc), c1p = dperm(cc + 1);
                C[(size_t)rr * N + c0p] = v0; C[(size_t)rr * N + c1p] = v1;
                C[(size_t)(rr + 8) * N + c0p] = v2; C[(size_t)(rr + 8) * N + c1p] = v3;
            } else {
                *(float2*)(C + (size_t)rr * N + cc) = make_float2(v0, v1);
                *(float2*)(C + (size_t)(rr + 8) * N + cc) = make_float2(v2, v3);
            }
        }
}

// ---------- fused co-attention branch: 2 e-tiles/warp, cp.async 3-stage ----------
// stage layout (floats): K[64*20]=1280 then V[16*68]=1088 -> 2368/stage, 3 stages
__global__ __launch_bounds__(256, 2) void k_branch_tc()
{
    __shared__ float sm[3 * 2368];
    uint32_t sb32 = (uint32_t)__cvta_generic_to_shared(sm);

    int eblk = blockIdx.x, b = blockIdx.y, r = blockIdx.z;
    int tid = threadIdx.x, lane = tid & 31, warp = tid >> 5;
    int g = lane >> 2, j = lane & 3;

    const float* gk  = g_K + (size_t)(r * 64 + b) * 16384;
    const float* gvb = g_V + (size_t)r * 655360 + (size_t)b * 10240;

    // J fragments for both e-tiles (loop-invariant); g_J pre-rounded
    float jf[2][2][4];
    {
        const float* jb = g_J + (size_t)b * 20480;
        int e0 = eblk * 256 + warp * 32 + g;
        #pragma unroll
        for (int tile = 0; tile < 2; ++tile) {
            int eT = e0 + tile * 16;
            jf[tile][0][0] = jb[(size_t)j * 2048 + eT];
            jf[tile][0][1] = jb[(size_t)j * 2048 + eT + 8];
            jf[tile][0][2] = jb[(size_t)(j + 4) * 2048 + eT];
            jf[tile][0][3] = jb[(size_t)(j + 4) * 2048 + eT + 8];
            jf[tile][1][0] = (j < 2) ? jb[(size_t)(8 + j) * 2048 + eT] : 0.f;
            jf[tile][1][1] = (j < 2) ? jb[(size_t)(8 + j) * 2048 + eT + 8] : 0.f;
            jf[tile][1][2] = 0.f; jf[tile][1][3] = 0.f;
        }
    }

    // zero V pad rows (t=10..15) in all stages
    for (int i = tid; i < 3 * 6 * 68; i += 256) {
        int st = i / 408, rem = i - st * 408;
        sm[st * 2368 + 1280 + (10 + rem / 68) * 68 + (rem % 68)] = 0.0f;
    }

    #define BR_ISSUE(CH, ST) do {                                               \
        uint32_t kb_ = sb32 + (uint32_t)(ST) * 2368u * 4u;                      \
        int d_ = tid >> 2, k4_ = (tid & 3) * 4;                                 \
        cpa16(kb_ + (uint32_t)(d_ * 20 + k4_) * 4u,                             \
              gk + (size_t)((CH) * 64 + d_) * 16 + k4_);                        \
        if (tid < 160) {                                                        \
            int t_ = tid >> 4, d4_ = (tid & 15) * 4;                            \
            cpa16(kb_ + (uint32_t)(1280 + t_ * 68 + d4_) * 4u,                  \
                  gvb + (size_t)t_ * 1024 + (CH) * 64 + d4_);                   \
        }                                                                       \
    } while (0)

    BR_ISSUE(0, 0); cpa_commit();
    BR_ISSUE(1, 1); cpa_commit();

    float accW[2][2][4] = {};

    for (int ch = 0; ch < 16; ++ch) {
        cpa_wait<1>();
        __syncthreads();
        if (ch + 2 < 16) { BR_ISSUE(ch + 2, (ch + 2) % 3); }
        cpa_commit();

        const float* Kb = sm + (ch % 3) * 2368;
        const float* Vb = Kb + 1280;

        #pragma unroll
        for (int dh = 0; dh < 2; ++dh) {
            float accS[2][4][4] = {};
            #pragma unroll
            for (int s = 0; s < 2; ++s) {
                int kk = s * 8 + j;
                #pragma unroll
                for (int ni = 0; ni < 4; ++ni) {
                    int dd = dh * 32 + ni * 8 + g;
                    float b0 = Kb[dd * 20 + kk], b1 = Kb[dd * 20 + kk + 4];
                    mma8(accS[0][ni], jf[0][s][0], jf[0][s][1], jf[0][s][2], jf[0][s][3], b0, b1);
                    mma8(accS[1][ni], jf[1][s][0], jf[1][s][1], jf[1][s][2], jf[1][s][3], b0, b1);
                }
            }
            #pragma unroll
            for (int ni = 0; ni < 4; ++ni) {
                float a0A = f2tf(tanhx(accS[0][ni][0]));
                float a1A = f2tf(tanhx(accS[0][ni][2]));
                float a2A = f2tf(tanhx(accS[0][ni][1]));
                float a3A = f2tf(tanhx(accS[0][ni][3]));
                float a0B = f2tf(tanhx(accS[1][ni][0]));
                float a1B = f2tf(tanhx(accS[1][ni][2]));
                float a2B = f2tf(tanhx(accS[1][ni][1]));
                float a3B = f2tf(tanhx(accS[1][ni][3]));
                #pragma unroll
                for (int nt = 0; nt < 2; ++nt) {
                    float2 bv = *(const float2*)&Vb[(nt * 8 + g) * 68 + dh * 32 + ni * 8 + 2 * j];
                    mma8(accW[0][nt], a0A, a1A, a2A, a3A, bv.x, bv.y);
                    mma8(accW[1][nt], a0B, a1B, a2B, a3B, bv.x, bv.y);
                }
            }
        }
    }
    #undef BR_ISSUE

    // epilogue: g_O = tf32(relu(tanh(accW)))
    #pragma unroll
    for (int tile = 0; tile < 2; ++tile) {
        int e = eblk * 256 + warp * 32 + tile * 16 + g;
        #pragma unroll
        for (int nt = 0; nt < 2; ++nt) {
            #pragma unroll
            for (int jj = 0; jj < 2; ++jj) {
                int t = nt * 8 + 2 * j + jj;
                if (t < 10) {
                    size_t rowoff = ((size_t)r * 640 + b * 10 + t) * 2048;
                    g_O[rowoff + e]     = f2tf(fmaxf(tanhx(accW[tile][nt][jj]), 0.0f));
                    g_O[rowoff + e + 8] = f2tf(fmaxf(tanhx(accW[tile][nt][2 + jj]), 0.0f));
                }
            }
        }
    }
}

// ---------- final: out = audio + video + fuse1 + fuse2 (float4) ----------
__global__ __launch_bounds__(256) void k_final(
    const float* __restrict__ audio, const float* __restrict__ video,
    float* __restrict__ out)
{
    int i = blockIdx.x * 256 + threadIdx.x;
    float4 a = ((const float4*)audio)[i];
    float4 v = ((const float4*)video)[i];
    float4 f1 = ((const float4*)g_F)[i];
    float4 f2 = ((const float4*)(g_F + 655360))[i];
    float4 o;
    o.x = a.x + v.x + f1.x + f2.x;
    o.y = a.y + v.y + f1.y + f2.y;
    o.z = a.z + v.z + f1.z + f2.z;
    o.w = a.w + v.w + f1.w + f2.w;
    ((float4*)out)[i] = o;
}

extern "C" void kernel_launch(void* const* d_in, const int* in_sizes, int n_in,
                              void* d_out, int out_size)
{
    const float* audio = (const float*)d_in[0];
    const float* video = (const float*)d_in[1];
    const float* Wq  = (const float*)d_in[2];
    const float* bq  = (const float*)d_in[3];
    const float* Wk1 = (const float*)d_in[4];
    const float* bk1 = (const float*)d_in[5];
    const float* Wk2 = (const float*)d_in[6];
    const float* bk2 = (const float*)d_in[7];
    const float* Wv1 = (const float*)d_in[8];
    const float* bv1 = (const float*)d_in[9];
    const float* Wv2 = (const float*)d_in[10];
    const float* bv2 = (const float*)d_in[11];
    const float* Wf  = (const float*)d_in[12];
    const float* bf  = (const float*)d_in[13];
    float* out = (float*)d_out;

    static float* wb = nullptr;
    if (!wb) {
        cudaGetSymbolAddress((void**)&wb, g_W);
        cudaFuncSetAttribute(k_gemm_tc, cudaFuncAttributeMaxDynamicSharedMemorySize, 53760);
    }

    // pre-round inputs + weights (tf32 RNA)
    k_round<<<9472, 256>>>(audio, video, Wq, Wv1, Wv2, Wf);
    // key linears (tiny, uses raw inputs)
    k_key<<<dim3(64, 2), 256>>>(audio, video, Wk1, bk1, Wk2, bk2);
    // joint = concat(audio,video) @ Wq + bq  [640x2048] K=2048 -> g_J (rounded)
    k_gemm_tc<<<dim3(32, 10), 256, 53760>>>(
        wb + OW_A, wb + OW_V, wb + OW_A, wb + OW_V, -1, 1024, 1024,
        wb + OW_WQ, wb + OW_WQ, bq, bq, 0, 0, 640, 2048, 2048, 0, 1, 0);
    // val1/val2 (z)  [640x1024] K=1024 -> g_V (rounded + d-permuted)
    k_gemm_tc<<<dim3(16, 10, 2), 256, 53760>>>(
        wb + OW_A, wb + OW_A, wb + OW_V, wb + OW_V, -1, 1024, 1024,
        wb + OW_WV1, wb + OW_WV2, bv1, bv2, 1, (size_t)640 * 1024,
        640, 1024, 1024, 0, 1, 1);
    // fused co-attention branches (2 e-tiles/warp)
    k_branch_tc<<<dim3(8, 64, 2), 256>>>();
    // fuse = relu(g_O @ Wf + bf)  [1280x1024] K=2048 -> g_F
    k_gemm_tc<<<dim3(16, 20), 256, 53760>>>(
        nullptr, nullptr, nullptr, nullptr, 3, 2048, 2048,
        wb + OW_WF, wb + OW_WF, bf, bf, 4, 0, 1280, 1024, 2048, 1, 0, 0);
    k_final<<<640, 256>>>(audio, video, out);
}

// round 9
// speedup vs baseline: 3.1983x; 1.0754x over previous
#include <cuda_runtime.h>
#include <cstdint>

#define DINL __device__ __forceinline__
#define SCALE_F 0.022097086912079608f  // 1/sqrt(2048)

// ---------- scratch ----------
__device__ float g_J[640 * 2048];            // joint, tf32-rounded
__device__ float g_K[2 * 64 * 1024 * 16];    // keys, SCALE folded, tf32, d-rows PERMUTED
__device__ float g_V[2 * 640 * 1024];        // values, tf32, d-cols PERMUTED
__device__ float g_O[2 * 640 * 2048];        // relu(tanh(weighted)), tf32-rounded
__device__ float g_W[9699328];               // pre-rounded: [audio|video|Wq|Wv1|Wv2|Wf]

// float offsets into g_W
#define OW_A   0
#define OW_V   655360
#define OW_WQ  1310720
#define OW_WV1 5505024
#define OW_WV2 6553600
#define OW_WF  7602176

DINL float tanhx(float x) {
    float y; asm("tanh.approx.f32 %0, %1;" : "=f"(y) : "f"(x)); return y;
}
DINL float f2tf(float x) {
    uint32_t r; asm("cvt.rna.tf32.f32 %0, %1;" : "=r"(r) : "f"(x));
    return __uint_as_float(r);
}
DINL void mma8(float* c, float a0, float a1, float a2, float a3, float b0, float b1) {
    asm volatile(
        "mma.sync.aligned.m16n8k8.row.col.f32.tf32.tf32.f32 "
        "{%0,%1,%2,%3},{%4,%5,%6,%7},{%8,%9},{%0,%1,%2,%3};"
        : "+f"(c[0]), "+f"(c[1]), "+f"(c[2]), "+f"(c[3])
        : "r"(__float_as_uint(a0)), "r"(__float_as_uint(a1)),
          "r"(__float_as_uint(a2)), "r"(__float_as_uint(a3)),
          "r"(__float_as_uint(b0)), "r"(__float_as_uint(b1)));
}
DINL int dperm(int c) {  // storage position of physical in-group index
    return (c & ~7) + 2 * (c & 3) + ((c & 7) >> 2);
}
DINL float* bufptr(int sel) {
    switch (sel) {
        case 0: return g_J;
        case 1: return g_V;
        default: return g_O;
    }
}
DINL void cpa16(uint32_t dst, const void* src) {
    asm volatile("cp.async.cg.shared.global [%0], [%1], 16;\n" :: "r"(dst), "l"(src));
}
DINL void cpa_commit() { asm volatile("cp.async.commit_group;\n" ::: "memory"); }
template<int W> DINL void cpa_wait() {
    asm volatile("cp.async.wait_group %0;\n" :: "n"(W) : "memory");
}

// ---------- pre-round inputs + weights into g_W ----------
__global__ __launch_bounds__(256) void k_round(
    const float* __restrict__ a, const float* __restrict__ v,
    const float* __restrict__ wq, const float* __restrict__ wv1,
    const float* __restrict__ wv2, const float* __restrict__ wf)
{
    int i = blockIdx.x * 256 + threadIdx.x;     // float4 index
    const float4* src; int base;
    if      (i <  163840) { src = (const float4*)a;   base = 0; }
    else if (i <  327680) { src = (const float4*)v;   base = 163840; }
    else if (i < 1376256) { src = (const float4*)wq;  base = 327680; }
    else if (i < 1638400) { src = (const float4*)wv1; base = 1376256; }
    else if (i < 1900544) { src = (const float4*)wv2; base = 1638400; }
    else                  { src = (const float4*)wf;  base = 1900544; }
    float4 x = src[i - base];
    x.x = f2tf(x.x); x.y = f2tf(x.y); x.z = f2tf(x.z); x.w = f2tf(x.w);
    ((float4*)g_W)[i] = x;
}

// ---------- key linears: permuted rows ----------
__global__ __launch_bounds__(256) void k_key(
    const float* __restrict__ audio, const float* __restrict__ video,
    const float* __restrict__ Wk1, const float* __restrict__ bk1,
    const float* __restrict__ Wk2, const float* __restrict__ bk2)
{
    int b = blockIdx.x, r = blockIdx.y;
    const float* X  = r ? video : audio;
    const float* Wk = r ? Wk2 : Wk1;
    const float* bk = r ? bk2 : bk1;
    __shared__ float sW[100], sb[10];
    if (threadIdx.x < 100) sW[threadIdx.x] = Wk[threadIdx.x];
    if (threadIdx.x < 10)  sb[threadIdx.x] = bk[threadIdx.x];
    __syncthreads();
    const float* xb = X + (size_t)b * 10240;
    float* kout = g_K + (size_t)(r * 64 + b) * 16384;
    for (int d = threadIdx.x; d < 1024; d += 256) {
        float a[10];
        #pragma unroll
        for (int t = 0; t < 10; ++t) a[t] = xb[t * 1024 + d];
        float* krow = kout + (size_t)dperm(d) * 16;
        #pragma unroll
        for (int t = 10; t < 16; ++t) krow[t] = 0.0f;
        #pragma unroll
        for (int t = 0; t < 10; ++t) {
            float s = sb[t];
            #pragma unroll
            for (int tp = 0; tp < 10; ++tp) s += a[tp] * sW[tp * 10 + t];
            krow[t] = f2tf(s * SCALE_F);
        }
    }
}

// ---------- tf32 GEMM: BM=64 BN=64 BK=32, 3-stage cp.async ----------
// stage layout (floats): A[64*36]=2304 then B[32*68]=2176 -> 4480/stage, 3 stages
__global__ __launch_bounds__(256) void k_gemm_tc(
    const float* A0, const float* A1, const float* A0z, const float* A1z,
    int aSel, int Asplit, int lda,
    const float* W0, const float* W1, const float* bias0, const float* bias1,
    int cSel, size_t cStride, int M, int N, int K,
    int doRelu, int doRound, int doPerm)
{
    extern __shared__ float smg[];
    uint32_t sb32 = (uint32_t)__cvta_generic_to_shared(smg);
    int z = blockIdx.z;
    const float* Ap0, *Ap1;
    if (aSel < 0) { Ap0 = z ? A0z : A0; Ap1 = z ? A1z : A1; }
    else          { Ap0 = Ap1 = bufptr(aSel); }
    const float* W    = z ? W1 : W0;
    const float* bias = z ? bias1 : bias0;
    float* C = bufptr(cSel) + (size_t)z * cStride;

    int tid = threadIdx.x, lane = tid & 31, warp = tid >> 5;
    int g = lane >> 2, j = lane & 3;
    int wm = (warp >> 2) * 32, wn = (warp & 3) * 16;
    int row0 = blockIdx.y * 64, col0 = blockIdx.x * 64;
    float acc[2][2][4] = {};

    int nt = K >> 5;

    #define GEMM_ISSUE(TI, ST) do {                                             \
        int kb_ = (TI) << 5;                                                    \
        uint32_t sA_ = sb32 + (uint32_t)(ST) * 4480u * 4u;                      \
        uint32_t sB_ = sA_ + 2304u * 4u;                                        \
        _Pragma("unroll")                                                       \
        for (int h_ = 0; h_ < 2; ++h_) {                                        \
            int c_ = h_ * 256 + tid;                                            \
            int ar_ = c_ >> 3, kg_ = (c_ & 7) * 4;                              \
            int gk_ = kb_ + kg_;                                                \
            const float* ap_ = (gk_ < Asplit)                                   \
                ? (Ap0 + (size_t)(row0 + ar_) * lda + gk_)                      \
                : (Ap1 + (size_t)(row0 + ar_) * lda + (gk_ - Asplit));          \
            cpa16(sA_ + (uint32_t)(ar_ * 36 + kg_) * 4u, ap_);                  \
        }                                                                       \
        _Pragma("unroll")                                                       \
        for (int h_ = 0; h_ < 2; ++h_) {                                        \
            int c_ = h_ * 256 + tid;                                            \
            int br_ = c_ >> 4, cg_ = (c_ & 15) * 4;                             \
            cpa16(sB_ + (uint32_t)(br_ * 68 + cg_) * 4u,                        \
                  W + (size_t)(kb_ + br_) * N + col0 + cg_);                    \
        }                                                                       \
    } while (0)

    // prologue: tiles 0,1
    if (0 < nt) { GEMM_ISSUE(0, 0); } cpa_commit();
    if (1 < nt) { GEMM_ISSUE(1, 1); } cpa_commit();

    for (int ti = 0; ti < nt; ++ti) {
        cpa_wait<1>();
        __syncthreads();
        int tin = ti + 2;
        if (tin < nt) { GEMM_ISSUE(tin, tin % 3); }
        cpa_commit();

        const float* Ab = smg + (ti % 3) * 4480;
        const float* Bb = Ab + 2304;
        #pragma unroll
        for (int ks = 0; ks < 32; ks += 8) {
            int kk = ks + j;
            float a[2][4];
            #pragma unroll
            for (int mi = 0; mi < 2; ++mi) {
                int rr = wm + mi * 16 + g;
                a[mi][0] = Ab[rr * 36 + kk];       a[mi][1] = Ab[(rr + 8) * 36 + kk];
                a[mi][2] = Ab[rr * 36 + kk + 4];   a[mi][3] = Ab[(rr + 8) * 36 + kk + 4];
            }
            #pragma unroll
            for (int ni = 0; ni < 2; ++ni) {
                int nn = wn + ni * 8 + g;
                float b0 = Bb[kk * 68 + nn], b1 = Bb[(kk + 4) * 68 + nn];
                mma8(acc[0][ni], a[0][0], a[0][1], a[0][2], a[0][3], b0, b1);
                mma8(acc[1][ni], a[1][0], a[1][1], a[1][2], a[1][3], b0, b1);
            }
        }
        // NOTE: no trailing __syncthreads — next iteration's top barrier
        // already orders reads of stage (ti-1)%3 before its overwrite.
    }
    #undef GEMM_ISSUE

    #pragma unroll
    for (int mi = 0; mi < 2; ++mi)
        #pragma unroll
        for (int ni = 0; ni < 2; ++ni) {
            int rr = row0 + wm + mi * 16 + g;
            int cc = col0 + wn + ni * 8 + 2 * j;
            float b0v = bias[cc], b1v = bias[cc + 1];
            float v0 = acc[mi][ni][0] + b0v, v1 = acc[mi][ni][1] + b1v;
            float v2 = acc[mi][ni][2] + b0v, v3 = acc[mi][ni][3] + b1v;
            if (doRelu) {
                v0 = fmaxf(v0, 0.f); v1 = fmaxf(v1, 0.f);
                v2 = fmaxf(v2, 0.f); v3 = fmaxf(v3, 0.f);
            }
            if (doRound) { v0 = f2tf(v0); v1 = f2tf(v1); v2 = f2tf(v2); v3 = f2tf(v3); }
            if (doPerm) {
                int c0p = dperm(cc), c1p = dperm(cc + 1);
                C[(size_t)rr * N + c0p] = v0; C[(size_t)rr * N + c1p] = v1;
                C[(size_t)(rr + 8) * N + c0p] = v2; C[(size_t)(rr + 8) * N + c1p] = v3;
            } else {
                *(float2*)(C + (size_t)rr * N + cc) = make_float2(v0, v1);
                *(float2*)(C + (size_t)(rr + 8) * N + cc) = make_float2(v2, v3);
            }
        }
}

// ---------- fused fc_fusion (both branches) + residual add -> d_out ----------
// Per CTA: rows m = row0..row0+31 of OUT; A0 = g_O rows m (branch 0),
// A1 = g_O rows 640+m (branch 1); B = Wf tile shared by both.
// out[m][c] = audio+video+relu(acc0+bf)+relu(acc1+bf).
// stage layout: A0[32*36]=1152, A1[32*36]=1152, B[32*68]=2176 -> 4480/stage x3
__global__ __launch_bounds__(256) void k_fuse(
    const float* __restrict__ audio, const float* __restrict__ video,
    const float* __restrict__ Wf, const float* __restrict__ bfb,
    float* __restrict__ out)
{
    extern __shared__ float smg[];
    uint32_t sb32 = (uint32_t)__cvta_generic_to_shared(smg);
    int tid = threadIdx.x, lane = tid & 31, warp = tid >> 5;
    int g = lane >> 2, j = lane & 3;
    int wm = (warp >> 2) * 16, wn = (warp & 3) * 16;
    int row0 = blockIdx.y * 32, col0 = blockIdx.x * 64;
    float acc[2][2][4] = {};   // [branch][ni][4]
    const int nt = 64;         // K = 2048

    #define FU_ISSUE(TI, ST) do {                                               \
        int kb_ = (TI) << 5;                                                    \
        uint32_t sA0_ = sb32 + (uint32_t)(ST) * 4480u * 4u;                     \
        uint32_t sA1_ = sA0_ + 1152u * 4u;                                      \
        uint32_t sB_  = sA1_ + 1152u * 4u;                                      \
        {                                                                       \
            int ar_ = tid >> 3, kg_ = (tid & 7) * 4;                            \
            cpa16(sA0_ + (uint32_t)(ar_ * 36 + kg_) * 4u,                       \
                  g_O + (size_t)(row0 + ar_) * 2048 + kb_ + kg_);               \
            cpa16(sA1_ + (uint32_t)(ar_ * 36 + kg_) * 4u,                       \
                  g_O + (size_t)(640 + row0 + ar_) * 2048 + kb_ + kg_);         \
        }                                                                       \
        _Pragma("unroll")                                                       \
        for (int h_ = 0; h_ < 2; ++h_) {                                        \
            int c_ = h_ * 256 + tid;                                            \
            int br_ = c_ >> 4, cg_ = (c_ & 15) * 4;                             \
            cpa16(sB_ + (uint32_t)(br_ * 68 + cg_) * 4u,                        \
                  Wf + (size_t)(kb_ + br_) * 1024 + col0 + cg_);                \
        }                                                                       \
    } while (0)

    FU_ISSUE(0, 0); cpa_commit();
    FU_ISSUE(1, 1); cpa_commit();

    for (int ti = 0; ti < nt; ++ti) {
        cpa_wait<1>();
        __syncthreads();
        int tin = ti + 2;
        if (tin < nt) { FU_ISSUE(tin, tin % 3); }
        cpa_commit();

        const float* S   = smg + (ti % 3) * 4480;
        const float* A0b = S;
        const float* A1b = S + 1152;
        const float* Bb  = S + 2304;
        #pragma unroll
        for (int ks = 0; ks < 32; ks += 8) {
            int kk = ks + j;
            int rr = wm + g;
            float a0[4], a1[4];
            a0[0] = A0b[rr * 36 + kk];     a0[1] = A0b[(rr + 8) * 36 + kk];
            a0[2] = A0b[rr * 36 + kk + 4]; a0[3] = A0b[(rr + 8) * 36 + kk + 4];
            a1[0] = A1b[rr * 36 + kk];     a1[1] = A1b[(rr + 8) * 36 + kk];
            a1[2] = A1b[rr * 36 + kk + 4]; a1[3] = A1b[(rr + 8) * 36 + kk + 4];
            #pragma unroll
            for (int ni = 0; ni < 2; ++ni) {
                int nn = wn + ni * 8 + g;
                float b0 = Bb[kk * 68 + nn], b1 = Bb[(kk + 4) * 68 + nn];
                mma8(acc[0][ni], a0[0], a0[1], a0[2], a0[3], b0, b1);
                mma8(acc[1][ni], a1[0], a1[1], a1[2], a1[3], b0, b1);
            }
        }
    }
    #undef FU_ISSUE

    #pragma unroll
    for (int ni = 0; ni < 2; ++ni) {
        int rr = row0 + wm + g, cc = col0 + wn + ni * 8 + 2 * j;
        float b0 = bfb[cc], b1 = bfb[cc + 1];
        size_t o0 = (size_t)rr * 1024 + cc, o1 = (size_t)(rr + 8) * 1024 + cc;
        float v0 = fmaxf(acc[0][ni][0] + b0, 0.f) + fmaxf(acc[1][ni][0] + b0, 0.f)
                 + audio[o0] + video[o0];
        float v1 = fmaxf(acc[0][ni][1] + b1, 0.f) + fmaxf(acc[1][ni][1] + b1, 0.f)
                 + audio[o0 + 1] + video[o0 + 1];
        float v2 = fmaxf(acc[0][ni][2] + b0, 0.f) + fmaxf(acc[1][ni][2] + b0, 0.f)
                 + audio[o1] + video[o1];
        float v3 = fmaxf(acc[0][ni][3] + b1, 0.f) + fmaxf(acc[1][ni][3] + b1, 0.f)
                 + audio[o1 + 1] + video[o1 + 1];
        *(float2*)(out + o0) = make_float2(v0, v1);
        *(float2*)(out + o1) = make_float2(v2, v3);
    }
}

// ---------- fused co-attention branch: 2 e-tiles/warp, cp.async 3-stage ----------
// stage layout (floats): K[64*20]=1280 then V[16*68]=1088 -> 2368/stage, 3 stages
__global__ __launch_bounds__(256, 2) void k_branch_tc()
{
    __shared__ float sm[3 * 2368];
    uint32_t sb32 = (uint32_t)__cvta_generic_to_shared(sm);

    int eblk = blockIdx.x, b = blockIdx.y, r = blockIdx.z;
    int tid = threadIdx.x, lane = tid & 31, warp = tid >> 5;
    int g = lane >> 2, j = lane & 3;

    const float* gk  = g_K + (size_t)(r * 64 + b) * 16384;
    const float* gvb = g_V + (size_t)r * 655360 + (size_t)b * 10240;

    // J fragments for both e-tiles (loop-invariant); g_J pre-rounded
    float jf[2][2][4];
    {
        const float* jb = g_J + (size_t)b * 20480;
        int e0 = eblk * 256 + warp * 32 + g;
        #pragma unroll
        for (int tile = 0; tile < 2; ++tile) {
            int eT = e0 + tile * 16;
            jf[tile][0][0] = jb[(size_t)j * 2048 + eT];
            jf[tile][0][1] = jb[(size_t)j * 2048 + eT + 8];
            jf[tile][0][2] = jb[(size_t)(j + 4) * 2048 + eT];
            jf[tile][0][3] = jb[(size_t)(j + 4) * 2048 + eT + 8];
            jf[tile][1][0] = (j < 2) ? jb[(size_t)(8 + j) * 2048 + eT] : 0.f;
            jf[tile][1][1] = (j < 2) ? jb[(size_t)(8 + j) * 2048 + eT + 8] : 0.f;
            jf[tile][1][2] = 0.f; jf[tile][1][3] = 0.f;
        }
    }

    // zero V pad rows (t=10..15) in all stages
    for (int i = tid; i < 3 * 6 * 68; i += 256) {
        int st = i / 408, rem = i - st * 408;
        sm[st * 2368 + 1280 + (10 + rem / 68) * 68 + (rem % 68)] = 0.0f;
    }

    #define BR_ISSUE(CH, ST) do {                                               \
        uint32_t kb_ = sb32 + (uint32_t)(ST) * 2368u * 4u;                      \
        int d_ = tid >> 2, k4_ = (tid & 3) * 4;                                 \
        cpa16(kb_ + (uint32_t)(d_ * 20 + k4_) * 4u,                             \
              gk + (size_t)((CH) * 64 + d_) * 16 + k4_);                        \
        if (tid < 160) {                                                        \
            int t_ = tid >> 4, d4_ = (tid & 15) * 4;                            \
            cpa16(kb_ + (uint32_t)(1280 + t_ * 68 + d4_) * 4u,                  \
                  gvb + (size_t)t_ * 1024 + (CH) * 64 + d4_);                   \
        }                                                                       \
    } while (0)

    BR_ISSUE(0, 0); cpa_commit();
    BR_ISSUE(1, 1); cpa_commit();

    float accW[2][2][4] = {};

    for (int ch = 0; ch < 16; ++ch) {
        cpa_wait<1>();
        __syncthreads();
        if (ch + 2 < 16) { BR_ISSUE(ch + 2, (ch + 2) % 3); }
        cpa_commit();

        const float* Kb = sm + (ch % 3) * 2368;
        const float* Vb = Kb + 1280;

        #pragma unroll
        for (int dh = 0; dh < 2; ++dh) {
            float accS[2][4][4] = {};
            #pragma unroll
            for (int s = 0; s < 2; ++s) {
                int kk = s * 8 + j;
                #pragma unroll
                for (int ni = 0; ni < 4; ++ni) {
                    int dd = dh * 32 + ni * 8 + g;
                    float b0 = Kb[dd * 20 + kk], b1 = Kb[dd * 20 + kk + 4];
                    mma8(accS[0][ni], jf[0][s][0], jf[0][s][1], jf[0][s][2], jf[0][s][3], b0, b1);
                    mma8(accS[1][ni], jf[1][s][0], jf[1][s][1], jf[1][s][2], jf[1][s][3], b0, b1);
                }
            }
            #pragma unroll
            for (int ni = 0; ni < 4; ++ni) {
                float a0A = f2tf(tanhx(accS[0][ni][0]));
                float a1A = f2tf(tanhx(accS[0][ni][2]));
                float a2A = f2tf(tanhx(accS[0][ni][1]));
                float a3A = f2tf(tanhx(accS[0][ni][3]));
                float a0B = f2tf(tanhx(accS[1][ni][0]));
                float a1B = f2tf(tanhx(accS[1][ni][2]));
                float a2B = f2tf(tanhx(accS[1][ni][1]));
                float a3B = f2tf(tanhx(accS[1][ni][3]));
                #pragma unroll
                for (int nt = 0; nt < 2; ++nt) {
                    float2 bv = *(const float2*)&Vb[(nt * 8 + g) * 68 + dh * 32 + ni * 8 + 2 * j];
                    mma8(accW[0][nt], a0A, a1A, a2A, a3A, bv.x, bv.y);
                    mma8(accW[1][nt], a0B, a1B, a2B, a3B, bv.x, bv.y);
                }
            }
        }
    }
    #undef BR_ISSUE

    // epilogue: g_O = tf32(relu(tanh(accW)))
    #pragma unroll
    for (int tile = 0; tile < 2; ++tile) {
        int e = eblk * 256 + warp * 32 + tile * 16 + g;
        #pragma unroll
        for (int nt = 0; nt < 2; ++nt) {
            #pragma unroll
            for (int jj = 0; jj < 2; ++jj) {
                int t = nt * 8 + 2 * j + jj;
                if (t < 10) {
                    size_t rowoff = ((size_t)r * 640 + b * 10 + t) * 2048;
                    g_O[rowoff + e]     = f2tf(fmaxf(tanhx(accW[tile][nt][jj]), 0.0f));
                    g_O[rowoff + e + 8] = f2tf(fmaxf(tanhx(accW[tile][nt][2 + jj]), 0.0f));
                }
            }
        }
    }
}

extern "C" void kernel_launch(void* const* d_in, const int* in_sizes, int n_in,
                              void* d_out, int out_size)
{
    const float* audio = (const float*)d_in[0];
    const float* video = (const float*)d_in[1];
    const float* Wq  = (const float*)d_in[2];
    const float* bq  = (const float*)d_in[3];
    const float* Wk1 = (const float*)d_in[4];
    const float* bk1 = (const float*)d_in[5];
    const float* Wk2 = (const float*)d_in[6];
    const float* bk2 = (const float*)d_in[7];
    const float* Wv1 = (const float*)d_in[8];
    const float* bv1 = (const float*)d_in[9];
    const float* Wv2 = (const float*)d_in[10];
    const float* bv2 = (const float*)d_in[11];
    const float* Wf  = (const float*)d_in[12];
    const float* bf  = (const float*)d_in[13];
    float* out = (float*)d_out;

    static float* wb = nullptr;
    static cudaStream_t s1 = nullptr, s2 = nullptr;
    static cudaEvent_t eS, eR, eK, eV;
    if (!wb) {
        cudaGetSymbolAddress((void**)&wb, g_W);
        cudaFuncSetAttribute(k_gemm_tc, cudaFuncAttributeMaxDynamicSharedMemorySize, 53760);
        cudaFuncSetAttribute(k_fuse,    cudaFuncAttributeMaxDynamicSharedMemorySize, 53760);
        cudaStreamCreateWithFlags(&s1, cudaStreamNonBlocking);
        cudaStreamCreateWithFlags(&s2, cudaStreamNonBlocking);
        cudaEventCreateWithFlags(&eS, cudaEventDisableTiming);
        cudaEventCreateWithFlags(&eR, cudaEventDisableTiming);
        cudaEventCreateWithFlags(&eK, cudaEventDisableTiming);
        cudaEventCreateWithFlags(&eV, cudaEventDisableTiming);
    }

    // fork: key linears on s2 (independent of k_round)
    cudaEventRecord(eS, 0);
    cudaStreamWaitEvent(s2, eS, 0);
    k_key<<<dim3(64, 2), 256, 0, s2>>>(audio, video, Wk1, bk1, Wk2, bk2);
    cudaEventRecord(eK, s2);

    // pre-round inputs + weights (tf32 RNA) on main stream
    k_round<<<9472, 256>>>(audio, video, Wq, Wv1, Wv2, Wf);
    cudaEventRecord(eR, 0);

    // val1/val2 on s1, concurrent with joint on main stream
    cudaStreamWaitEvent(s1, eR, 0);
    k_gemm_tc<<<dim3(16, 10, 2), 256, 53760, s1>>>(
        wb + OW_A, wb + OW_A, wb + OW_V, wb + OW_V, -1, 1024, 1024,
        wb + OW_WV1, wb + OW_WV2, bv1, bv2, 1, (size_t)640 * 1024,
        640, 1024, 1024, 0, 1, 1);
    cudaEventRecord(eV, s1);

    // joint = concat(audio,video) @ Wq + bq  [640x2048] K=2048 -> g_J (rounded)
    k_gemm_tc<<<dim3(32, 10), 256, 53760>>>(
        wb + OW_A, wb + OW_V, wb + OW_A, wb + OW_V, -1, 1024, 1024,
        wb + OW_WQ, wb + OW_WQ, bq, bq, 0, 0, 640, 2048, 2048, 0, 1, 0);

    // join: branch needs joint + val + key
    cudaStreamWaitEvent(0, eV, 0);
    cudaStreamWaitEvent(0, eK, 0);
    k_branch_tc<<<dim3(8, 64, 2), 256>>>();

    // fused fc_fusion (both branches) + residual -> d_out
    k_fuse<<<dim3(16, 20), 256, 53760>>>(audio, video, wb + OW_WF, bf, out);
}